// round 13
// baseline (speedup 1.0000x reference)
#include <cuda_runtime.h>
#include <cuda_fp16.h>
#include <cstdint>

// ---------------- problem constants ----------------
#define Bsz 512
#define Wln 50
#define Tln 50
#define Hd  1024
#define Vb  1024
#define MVd 64
#define Ld  30
#define G4H 4096
#define SOS_INDEX 0
#define EOS_INDEX 1

#define PLANE_B 16384
#define BLKB    32768
#define BLKE    16384
#define GRID_N  256

// ---------------- scratch ----------------
__device__ float d_c   [Bsz * Hd];
__device__ float d_mm  [Ld * Bsz];
__device__ float d_m   [Bsz];
__device__ float d_hA32[Bsz * Hd];
__device__ float d_hB32[Bsz * Hd];
__device__ float pb_set[G4H], pb_gen[G4H], pb_menc[G4H], pb_dec[G4H];
__device__ unsigned g_cnt, g_epoch;
__device__ float pg_menc[Ld * Bsz * G4H];
__device__ float d_ptab [Vb * G4H];

#define TLA __align__(1024)
__device__ TLA __half e_tl   [128 * BLKE];
__device__ TLA __half wset_tl[512 * BLKE];
__device__ TLA __half wgen_tl[512 * BLKE];
__device__ TLA __half wmi_tl [32  * BLKE];
__device__ TLA __half wmh_tl [512 * BLKE];
__device__ TLA __half wdi_tl [512 * BLKE];
__device__ TLA __half wdh_tl [512 * BLKE];
__device__ TLA __half wo_tl  [128 * BLKE];
__device__ TLA __half hA_tl  [64  * BLKE];
__device__ TLA __half hB_tl  [64  * BLKE];
__device__ TLA __half r_tl   [64  * BLKE];
__device__ TLA __half msg_tl [Ld * 4 * BLKE];
__device__ TLA __half hall_tl[Tln * 64 * BLKE];

// ---------------- ptx helpers ----------------
__device__ __forceinline__ uint32_t smem_to_u32(const void* p) {
    uint32_t a;
    asm("{ .reg .u64 t; cvta.to.shared.u64 t, %1; cvt.u32.u64 %0, t; }" : "=r"(a) : "l"(p));
    return a;
}
#define CP_ASYNC16(dst, src) \
    asm volatile("cp.async.cg.shared.global [%0], [%1], 16;" :: "r"(dst), "l"(src))
#define CP_COMMIT() asm volatile("cp.async.commit_group;" ::: "memory")
#define CP_WAIT0()  asm volatile("cp.async.wait_group 0;" ::: "memory")
#define CP_WAIT1()  asm volatile("cp.async.wait_group 1;" ::: "memory")
#define LDSM4(r, a) \
    asm volatile("ldmatrix.sync.aligned.m8n8.x4.shared.b16 {%0,%1,%2,%3}, [%4];" \
        : "=r"((r)[0]), "=r"((r)[1]), "=r"((r)[2]), "=r"((r)[3]) : "r"(a))
#define SWZ(x) ((x) ^ (((x) >> 3) & 0x70))

__device__ __forceinline__ void mma_f16(float* c, const uint32_t* a, const uint32_t* b)
{
    asm volatile(
        "mma.sync.aligned.m16n8k16.row.col.f32.f16.f16.f32 "
        "{%0,%1,%2,%3}, {%4,%5,%6,%7}, {%8,%9}, {%0,%1,%2,%3};\n"
        : "+f"(c[0]), "+f"(c[1]), "+f"(c[2]), "+f"(c[3])
        : "r"(a[0]), "r"(a[1]), "r"(a[2]), "r"(a[3]), "r"(b[0]), "r"(b[1]));
}

__device__ __forceinline__ size_t tlo(int row, int kelem, int KB)
{
    return ((size_t)(row >> 7) * KB + (kelem >> 6)) * BLKB +
           (size_t)SWZ((uint32_t)(((row & 127) << 7) | ((kelem & 63) << 1)));
}

// ---------------- smem layout ----------------
#define SM_TILES  1024
#define NSTAGE    3
#define SGPAD     129
#define STAGE64_B 24576
#define SMEM_P    (SM_TILES + NSTAGE * STAGE64_B)
#define SMEM_N1   (SM_TILES + NSTAGE * 2 * PLANE_B)

// ---------------- grid barrier ----------------
__device__ __forceinline__ void gbar(unsigned& tgt)
{
    __syncthreads();
    if (threadIdx.x == 0) {
        __threadfence();
        unsigned v = atomicAdd(&g_cnt, 1u);
        if ((v & (GRID_N - 1)) == (GRID_N - 1)) {
            __threadfence();
            atomicAdd(&g_epoch, 1u);
        } else {
            unsigned e;
            do {
                asm volatile("ld.acquire.gpu.global.u32 %0, [%1];"
                             : "=r"(e) : "l"(&g_epoch));
            } while ((int)(e - tgt) < 0);
        }
        __threadfence();
    }
    __syncthreads();
    tgt++;
}

// ---------------- 64x128 1-product GEMM mainloop -----------------------------
__device__ __forceinline__ void gemm_part64(
    float (&acc)[2][4][4], uint32_t sb,
    const char* __restrict__ atl, int ablk,
    const char* __restrict__ wtl, int KB,
    int bm, int bn, int tid)
{
    __syncthreads();
    const uint32_t ahalf = ((uint32_t)(bm >> 6) & 1u) * 8192u;
    auto issue = [&](int kb) {
        const uint32_t stage = sb + SM_TILES + (kb % NSTAGE) * STAGE64_B;
        const char* asrc = atl + ((size_t)(ablk + (bm >> 7) * KB + kb)) * BLKB + ahalf;
        const char* wsrc = wtl + ((size_t)((bn >> 7) * KB + kb)) * BLKB;
        uint32_t ao = (uint32_t)tid * 32;
        CP_ASYNC16(stage + ao,      asrc + ao);
        CP_ASYNC16(stage + ao + 16, asrc + ao + 16);
        uint32_t wo = (uint32_t)tid * 64;
        #pragma unroll
        for (int j = 0; j < 4; j++)
            CP_ASYNC16(stage + 8192 + wo + j * 16, wsrc + wo + j * 16);
        CP_COMMIT();
    };
    issue(0);
    if (KB > 1) issue(1);
    const int wid = tid >> 5, lane = tid & 31;
    const int wm = (wid >> 2) * 32, wn = (wid & 3) * 32;
    for (int kb = 0; kb < KB; kb++) {
        if (kb + 1 < KB) { CP_WAIT1(); } else { CP_WAIT0(); }
        __syncthreads();
        if (kb + 2 < KB) issue(kb + 2);
        const uint32_t stage = sb + SM_TILES + (kb % NSTAGE) * STAGE64_B;
        #pragma unroll
        for (int ks = 0; ks < 4; ks++) {
            uint32_t ah[2][4], bh[4][2];
            {
                const int arow = wm + (lane & 15);
                const int acol = ks * 32 + ((lane >> 4) << 4);
                #pragma unroll
                for (int mt = 0; mt < 2; mt++) {
                    uint32_t off = SWZ((uint32_t)((arow + mt * 16) * 128 + acol));
                    LDSM4(ah[mt], stage + off);
                }
            }
            {
                const int brow = wn + (lane & 7) + ((lane >> 4) << 3);
                const int bcol = ks * 32 + (((lane >> 3) & 1) << 4);
                #pragma unroll
                for (int p2 = 0; p2 < 2; p2++) {
                    uint32_t off = SWZ((uint32_t)((brow + p2 * 16) * 128 + bcol));
                    uint32_t r[4];
                    LDSM4(r, stage + 8192 + off);
                    bh[p2 * 2][0] = r[0]; bh[p2 * 2][1] = r[1];
                    bh[p2 * 2 + 1][0] = r[2]; bh[p2 * 2 + 1][1] = r[3];
                }
            }
            #pragma unroll
            for (int mt = 0; mt < 2; mt++)
                #pragma unroll
                for (int nt = 0; nt < 4; nt++)
                    mma_f16(acc[mt][nt], ah[mt], bh[nt]);
        }
    }
}

// ---------------- 64-row fused LSTM epilogue ---------------------------------
__device__ __forceinline__ void lstm_epi64(
    float (&acc)[2][4][4], char* smem,
    const float* __restrict__ bias, const float* __restrict__ pg,
    const float* __restrict__ ptab, const int* __restrict__ gidx,
    const float* __restrict__ c_in, float* __restrict__ c_out,
    float* __restrict__ h_f32, char* __restrict__ ht,
    const float* __restrict__ maskp, const float* __restrict__ h_old,
    int bm, int bn, int tid)
{
    const int wid = tid >> 5, lane = tid & 31;
    const int wm = (wid >> 2) * 32, wn = (wid & 3) * 32;
    const bool use_pg = (pg != nullptr) || (ptab != nullptr);
    __syncthreads();
    float* sg = (float*)(smem + SM_TILES);
    #pragma unroll
    for (int nt = 0; nt < 4; nt++) {
        const int ln = wn + nt * 8 + 2 * (lane & 3);
        const float bias0 = use_pg ? 0.f : bias[bn + ln];
        const float bias1 = use_pg ? 0.f : bias[bn + ln + 1];
        #pragma unroll
        for (int mt = 0; mt < 2; mt++) {
            const int lm = wm + mt * 16 + (lane >> 2);
            sg[lm * SGPAD + ln]           = acc[mt][nt][0] + bias0;
            sg[lm * SGPAD + ln + 1]       = acc[mt][nt][1] + bias1;
            sg[(lm + 8) * SGPAD + ln]     = acc[mt][nt][2] + bias0;
            sg[(lm + 8) * SGPAD + ln + 1] = acc[mt][nt][3] + bias1;
        }
    }
    __syncthreads();

    const int gu_base = bn >> 2;
    for (int i = tid; i < 64 * 32; i += 256) {
        const int u = i & 31, mrow = i >> 5;
        const float* row = sg + mrow * SGPAD + u * 4;
        float gi_ = row[0], gf_ = row[1], gg_ = row[2], go_ = row[3];
        const int gm = bm + mrow;
        const int ug = gu_base + u;
        if (ptab) {
            int rid = gidx ? gidx[gm] : SOS_INDEX;
            float4 pv = *(const float4*)(ptab + (size_t)rid * G4H + ug * 4);
            gi_ += pv.x; gf_ += pv.y; gg_ += pv.z; go_ += pv.w;
        } else if (pg) {
            float4 pv = *(const float4*)(pg + (size_t)gm * G4H + ug * 4);
            gi_ += pv.x; gf_ += pv.y; gg_ += pv.z; go_ += pv.w;
        }
        const size_t ci = (size_t)gm * Hd + ug;
        float cold = c_in ? c_in[ci] : 0.f;
        float si = 1.f / (1.f + expf(-gi_));
        float sf = 1.f / (1.f + expf(-gf_));
        float so = 1.f / (1.f + expf(-go_));
        float cn = sf * cold + si * tanhf(gg_);
        float hn = so * tanhf(cn);
        if (maskp) {
            float mt_ = maskp[gm];
            hn = mt_ * hn + (1.f - mt_) * h_old[ci];
            cn = mt_ * cn + (1.f - mt_) * cold;
        }
        c_out[ci] = cn;
        if (h_f32) h_f32[ci] = hn;
        __half hb = __float2half_rn(hn);
        __half lb = __float2half_rn(hn - __half2float(hb));
        size_t bo = tlo(gm, ug, 16);
        *(__half*)(ht + bo) = hb;
        *(__half*)(ht + bo + PLANE_B) = lb;
    }
}

// ---------------- in-kernel gen output head (8 rows per CTA, 64 CTAs) --------
__device__ __forceinline__ void gen_out_phase8(
    char* smem, const float* __restrict__ qf,
    const float* __restrict__ outW, const float* __restrict__ outb,
    char* __restrict__ msg_l, float* __restrict__ mm_l, float* __restrict__ m_state,
    int cta, int tid)
{
    float* hs = (float*)(smem + SM_TILES);            // 8 x 1024 fp32
    const int wid = tid >> 5, lane = tid & 31;
    const int row = cta * 8 + wid;                    // one warp per row
    {
        float4* dst = (float4*)(hs + wid * Hd);
        const float4* src = (const float4*)(qf + (size_t)row * Hd);
        for (int k = lane; k < Hd / 4; k += 32) dst[k] = src[k];
    }
    __syncwarp();

    const int j0 = lane, j1 = lane + 32;
    float acc0 = outb[j0], acc1 = outb[j1];
    const float4* h4 = (const float4*)(hs + wid * Hd);
    const float4* w0 = (const float4*)(outW + (size_t)j0 * Hd);
    const float4* w1 = (const float4*)(outW + (size_t)j1 * Hd);
    #pragma unroll 4
    for (int k = 0; k < Hd / 4; k++) {
        float4 hv = h4[k];
        float4 wv = w0[k];
        acc0 += wv.x * hv.x + wv.y * hv.y + wv.z * hv.z + wv.w * hv.w;
        wv = w1[k];
        acc1 += wv.x * hv.x + wv.y * hv.y + wv.z * hv.z + wv.w * hv.w;
    }
    float vmax = fmaxf(acc0, acc1);
    #pragma unroll
    for (int o = 16; o; o >>= 1) vmax = fmaxf(vmax, __shfl_xor_sync(0xffffffffu, vmax, o));
    float e0 = expf(acc0 - vmax), e1 = expf(acc1 - vmax);
    float ss = e0 + e1;
    #pragma unroll
    for (int o = 16; o; o >>= 1) ss += __shfl_xor_sync(0xffffffffu, ss, o);
    float p0 = e0 / ss, p1 = e1 / ss;

    {
        __half pb = __float2half_rn(p0);
        size_t bo = tlo(row, j0, 1);
        *(__half*)(msg_l + bo) = pb;
        *(__half*)(msg_l + bo + PLANE_B) = __float2half_rn(p0 - __half2float(pb));
        pb = __float2half_rn(p1);
        bo = tlo(row, j1, 1);
        *(__half*)(msg_l + bo) = pb;
        *(__half*)(msg_l + bo + PLANE_B) = __float2half_rn(p1 - __half2float(pb));
    }
    if (lane == EOS_INDEX) {
        float mo = m_state[row];
        mm_l[row] = mo;
        m_state[row] = mo * (1.f - p0);
    }
}

#define ZERO_ACC2(acc) { \
    _Pragma("unroll") for (int mt = 0; mt < 2; mt++) \
    _Pragma("unroll") for (int nt = 0; nt < 4; nt++) \
    _Pragma("unroll") for (int i = 0; i < 4; i++) acc[mt][nt][i] = 0.f; }
#define ZERO_ACC4(acc) { \
    _Pragma("unroll") for (int mt = 0; mt < 4; mt++) \
    _Pragma("unroll") for (int nt = 0; nt < 4; nt++) \
    _Pragma("unroll") for (int i = 0; i < 4; i++) acc[mt][nt][i] = 0.f; }

// ---------------- persistent loop kernels ------------------------------------
__global__ void __launch_bounds__(256, 2)
gen_loop(const __half* __restrict__ wg, const float* __restrict__ bias,
         const float* __restrict__ outW, const float* __restrict__ outb,
         float* c, float* mm, float* m,
         __half* hA, __half* hB, float* fA, float* fB, __half* msg)
{
    extern __shared__ char smem[];
    const uint32_t sb = smem_to_u32(smem);
    const int tid = threadIdx.x;
    const int bm = blockIdx.y * 64, bn = blockIdx.x * 128;
    const int cta = blockIdx.y * 32 + blockIdx.x;
    unsigned tgt = *((volatile unsigned*)&g_epoch) + 1;
    const char* pt = (const char*)hA;
    char* qt = (char*)hB;
    float* qf = fB;
    float* of = fA;
    float acc[2][4][4];
    for (int l = 0; l < Ld; l++) {
        ZERO_ACC2(acc);
        gemm_part64(acc, sb, pt, 0, (const char*)wg, 16, bm, bn, tid);
        lstm_epi64(acc, smem, bias, nullptr, nullptr, nullptr,
                   c, c, qf, qt, nullptr, nullptr, bm, bn, tid);
        gbar(tgt);
        if (cta < 64)
            gen_out_phase8(smem, qf, outW, outb,
                           (char*)msg + (size_t)l * 4 * BLKB, mm + l * Bsz, m, cta, tid);
        { const char* t = pt; pt = qt; qt = (char*)t; }
        { float* t = qf; qf = of; of = t; }
    }
}

__global__ void __launch_bounds__(256, 2)
menc_loop(const __half* __restrict__ wmh, const float* __restrict__ pgm,
          float* c, const float* __restrict__ mm,
          __half* hA, __half* hB, float* fA, float* fB)
{
    extern __shared__ char smem[];
    const uint32_t sb = smem_to_u32(smem);
    const int tid = threadIdx.x;
    const int bm = blockIdx.y * 64, bn = blockIdx.x * 128;
    unsigned tgt = *((volatile unsigned*)&g_epoch) + 1;
    const char* pt = (const char*)hA;
    char* qt = (char*)hB;
    const float* pf = fA;
    float* qf = fB;
    float acc[2][4][4];
    for (int l = 0; l < Ld; l++) {
        ZERO_ACC2(acc);
        gbar(tgt);
        gemm_part64(acc, sb, pt, 0, (const char*)wmh, 16, bm, bn, tid);
        lstm_epi64(acc, smem, nullptr, pgm + (size_t)l * Bsz * G4H, nullptr, nullptr,
                   c, c, qf, qt, mm + l * Bsz, pf, bm, bn, tid);
        { const char* t = pt; pt = qt; qt = (char*)t; }
        { const float* t = pf; pf = qf; qf = (float*)t; }
    }
}

__global__ void __launch_bounds__(256, 2)
dec_loop(const __half* __restrict__ wdh, const float* __restrict__ ptab,
         const int* __restrict__ tgt_var,
         float* c, const __half* __restrict__ h0t, __half* hallt)
{
    extern __shared__ char smem[];
    const uint32_t sb = smem_to_u32(smem);
    const int tid = threadIdx.x;
    const int bm = blockIdx.y * 64, bn = blockIdx.x * 128;
    unsigned tgt = *((volatile unsigned*)&g_epoch) + 1;
    float acc[2][4][4];
    for (int t = 0; t < Tln; t++) {
        ZERO_ACC2(acc);
        gbar(tgt);
        const char* a2 = (t == 0) ? (const char*)h0t : (const char*)hallt;
        int ab = (t == 0) ? 0 : (t - 1) * 64;
        gemm_part64(acc, sb, a2, ab, (const char*)wdh, 16, bm, bn, tid);
        const int* gidx = (t == 0) ? nullptr : (tgt_var + (size_t)(t - 1) * Bsz);
        lstm_epi64(acc, smem, nullptr, nullptr, ptab, gidx,
                   c, c, nullptr,
                   (char*)hallt + (size_t)t * 64 * BLKB, nullptr, nullptr, bm, bn, tid);
    }
}

// ---------------- standalone GEMM kernel (1-product, 128x128 tiles) ----------
__global__ void __launch_bounds__(256, 2)
gemm_tc1(float* __restrict__ C, int N,
         const __half* __restrict__ a1, int a1base,
         const __half* __restrict__ w1, int KB1,
         const float* __restrict__ bias, int mode,
         float* __restrict__ c_out, float* __restrict__ h_f32,
         __half* __restrict__ ht_out)
{
    extern __shared__ char smem[];
    const uint32_t sb = smem_to_u32(smem);
    const int bm = blockIdx.y * 128, bn = blockIdx.x * 128;
    const int tid = threadIdx.x, wid = tid >> 5, lane = tid & 31;
    const int wm = (wid >> 2) * 64;
    const int wn = (wid & 3) * 32;
    const int nb = KB1;

    auto issue = [&](int kb) {
        const uint32_t stage = sb + SM_TILES + (kb % NSTAGE) * (2 * PLANE_B);
        const char* asrc = (const char*)a1 + ((size_t)(a1base + (bm >> 7) * KB1 + kb)) * BLKB;
        const char* wsrc = (const char*)w1 + ((size_t)((bn >> 7) * KB1 + kb)) * BLKB;
        #pragma unroll
        for (int j = 0; j < 4; j++) {
            uint32_t off = (uint32_t)(tid * 4 + j) * 16;
            CP_ASYNC16(stage + off, asrc + off);
            CP_ASYNC16(stage + PLANE_B + off, wsrc + off);
        }
        CP_COMMIT();
    };

    float acc[4][4][4];
    ZERO_ACC4(acc);

    issue(0);
    if (nb > 1) issue(1);

    for (int kb = 0; kb < nb; kb++) {
        if (kb + 1 < nb) { CP_WAIT1(); } else { CP_WAIT0(); }
        __syncthreads();
        if (kb + 2 < nb) issue(kb + 2);
        const uint32_t stage = sb + SM_TILES + (kb % NSTAGE) * (2 * PLANE_B);

        #pragma unroll
        for (int ks = 0; ks < 4; ks++) {
            uint32_t ah[4][4], bh[4][2];
            {
                const int arow = wm + (lane & 15);
                const int acol = ks * 32 + ((lane >> 4) << 4);
                #pragma unroll
                for (int mt = 0; mt < 4; mt++) {
                    uint32_t off = SWZ((uint32_t)((arow + mt * 16) * 128 + acol));
                    LDSM4(ah[mt], stage + off);
                }
            }
            {
                const int brow = wn + (lane & 7) + ((lane >> 4) << 3);
                const int bcol = ks * 32 + (((lane >> 3) & 1) << 4);
                #pragma unroll
                for (int p2 = 0; p2 < 2; p2++) {
                    uint32_t off = SWZ((uint32_t)((brow + p2 * 16) * 128 + bcol));
                    uint32_t r[4];
                    LDSM4(r, stage + PLANE_B + off);
                    bh[p2 * 2][0] = r[0]; bh[p2 * 2][1] = r[1];
                    bh[p2 * 2 + 1][0] = r[2]; bh[p2 * 2 + 1][1] = r[3];
                }
            }
            #pragma unroll
            for (int mt = 0; mt < 4; mt++)
                #pragma unroll
                for (int nt = 0; nt < 4; nt++)
                    mma_f16(acc[mt][nt], ah[mt], bh[nt]);
        }
    }

    if (mode == 0) {
        #pragma unroll
        for (int nt = 0; nt < 4; nt++) {
            const int n0 = bn + wn + nt * 8 + 2 * (lane & 3);
            float bias0 = bias ? bias[n0] : 0.f;
            float bias1 = bias ? bias[n0 + 1] : 0.f;
            #pragma unroll
            for (int mt = 0; mt < 4; mt++) {
                const int m0 = bm + wm + mt * 16 + (lane >> 2);
                float2 v0 = make_float2(acc[mt][nt][0] + bias0, acc[mt][nt][1] + bias1);
                float2 v1 = make_float2(acc[mt][nt][2] + bias0, acc[mt][nt][3] + bias1);
                *(float2*)&C[(size_t)m0 * N + n0] = v0;
                *(float2*)&C[(size_t)(m0 + 8) * N + n0] = v1;
            }
        }
        return;
    }

    // 128-row fused LSTM epilogue (set encoder; c_in == 0)
    __syncthreads();
    float* sg = (float*)(smem + SM_TILES);
    #pragma unroll
    for (int nt = 0; nt < 4; nt++) {
        const int ln = wn + nt * 8 + 2 * (lane & 3);
        const float bias0 = bias[bn + ln];
        const float bias1 = bias[bn + ln + 1];
        #pragma unroll
        for (int mt = 0; mt < 4; mt++) {
            const int lm = wm + mt * 16 + (lane >> 2);
            sg[lm * SGPAD + ln]           = acc[mt][nt][0] + bias0;
            sg[lm * SGPAD + ln + 1]       = acc[mt][nt][1] + bias1;
            sg[(lm + 8) * SGPAD + ln]     = acc[mt][nt][2] + bias0;
            sg[(lm + 8) * SGPAD + ln + 1] = acc[mt][nt][3] + bias1;
        }
    }
    __syncthreads();
    const int gu_base = bn >> 2;
    char* ht = (char*)ht_out;
    for (int i = tid; i < 128 * 32; i += 256) {
        const int u = i & 31, mrow = i >> 5;
        const float* row = sg + mrow * SGPAD + u * 4;
        float gi_ = row[0], gf_ = row[1], gg_ = row[2], go_ = row[3];
        const int gm = bm + mrow;
        const int ug = gu_base + u;
        const size_t ci = (size_t)gm * Hd + ug;
        float si = 1.f / (1.f + expf(-gi_));
        float sf = 1.f / (1.f + expf(-gf_));
        float so = 1.f / (1.f + expf(-go_));
        float cn = si * tanhf(gg_);
        (void)sf;
        float hn = so * tanhf(cn);
        c_out[ci] = cn;
        if (h_f32) h_f32[ci] = hn;
        __half hb = __float2half_rn(hn);
        __half lb = __float2half_rn(hn - __half2float(hb));
        size_t bo = tlo(gm, ug, 16);
        *(__half*)(ht + bo) = hb;
        *(__half*)(ht + bo + PLANE_B) = lb;
    }
}

// ---------------- conversion / pre-tiling kernels ----------------
__device__ __forceinline__ void conv_perm_one(const float* s, __half* dst, int K, int i)
{
    int np = i / K, k = i - np * K;
    int u = np >> 2, g = np & 3;
    float x = s[(size_t)(g * Hd + u) * K + k];
    __half h = __float2half_rn(x);
    size_t bo = tlo(np, k, K >> 6);
    char* d = (char*)dst;
    *(__half*)(d + bo) = h;
    *(__half*)(d + bo + PLANE_B) = __float2half_rn(x - __half2float(h));
}

__global__ void conv_perm_tl(const float* __restrict__ s, __half* __restrict__ dst, int K)
{
    int i = blockIdx.x * blockDim.x + threadIdx.x;
    if (i >= G4H * K) return;
    conv_perm_one(s, dst, K, i);
}

// fused: two G4HxHd permuted conversions in one launch
__global__ void conv_pair_perm(const float* __restrict__ s0, __half* __restrict__ d0,
                               const float* __restrict__ s1, __half* __restrict__ d1)
{
    int i = blockIdx.x * blockDim.x + threadIdx.x;
    if (i < G4H * Hd) conv_perm_one(s0, d0, Hd, i);
    else if (i < 2 * G4H * Hd) conv_perm_one(s1, d1, Hd, i - G4H * Hd);
}

__global__ void conv_tl(const float* __restrict__ s, __half* __restrict__ dst,
                        int rows, int K)
{
    int i = blockIdx.x * blockDim.x + threadIdx.x;
    if (i >= rows * K) return;
    int np = i / K, k = i - np * K;
    float x = s[(size_t)np * K + k];
    __half h = __float2half_rn(x);
    size_t bo = tlo(np, k, K >> 6);
    char* d = (char*)dst;
    *(__half*)(d + bo) = h;
    *(__half*)(d + bo + PLANE_B) = __float2half_rn(x - __half2float(h));
}

// fused: attention (blocks 0..511) + bias prep / m fill (blocks 512+)
__global__ void prep_attn(const int* __restrict__ inp, const float* __restrict__ mask,
                          const float* __restrict__ emb, const float* __restrict__ attn_w,
                          const float* __restrict__ attn_b, __half* __restrict__ rtl,
                          const float* sb1, const float* sb2, float* so,
                          const float* gb1, const float* gb2, float* go,
                          const float* mb1, const float* mb2, float* mo,
                          const float* db1, const float* db2, float* dopt,
                          float* m)
{
    __shared__ float aw[Wln];
    __shared__ int   idxs[Wln];
    const int tid = threadIdx.x;

    if (blockIdx.x >= Bsz) {
        int i = (blockIdx.x - Bsz) * 256 + tid;
        if (i < 4 * G4H) {
            int set = i >> 12, np = i & (G4H - 1);
            int u = np >> 2, g = np & 3;
            int src = g * Hd + u;
            float v; float* o;
            if (set == 0)      { v = sb1[src] + sb2[src]; o = so; }
            else if (set == 1) { v = gb1[src] + gb2[src]; o = go; }
            else if (set == 2) { v = mb1[src] + mb2[src]; o = mo; }
            else               { v = db1[src] + db2[src]; o = dopt; }
            o[np] = v;
        } else if (i < 4 * G4H + Bsz) {
            m[i - 4 * G4H] = 1.f;
        }
        return;
    }

    const int b = blockIdx.x;
    const int lane = tid & 31, wrp = tid >> 5;
    if (tid < Wln) idxs[tid] = inp[b * Wln + tid];
    __syncthreads();
    const float* w2 = attn_w + Hd;
    for (int wi = wrp; wi < Wln; wi += 8) {
        const float* e = emb + (size_t)idxs[wi] * Hd;
        float acc = 0.f;
        for (int k = lane; k < Hd; k += 32) acc += e[k] * w2[k];
        #pragma unroll
        for (int o = 16; o; o >>= 1) acc += __shfl_xor_sync(0xffffffffu, acc, o);
        if (lane == 0) {
            float a = 1.f / (1.f + expf(-(acc + attn_b[0])));
            aw[wi] = a * mask[wi * Bsz + b];
        }
    }
    __syncthreads();
    char* d = (char*)rtl;
    for (int hh = tid; hh < Hd; hh += 256) {
        float acc = 0.f;
        #pragma unroll 5
        for (int wi = 0; wi < Wln; wi++)
            acc += aw[wi] * emb[(size_t)idxs[wi] * Hd + hh];
        __half hb = __float2half_rn(acc);
        size_t bo = tlo(b, hh, 16);
        *(__half*)(d + bo) = hb;
        *(__half*)(d + bo + PLANE_B) = __float2half_rn(acc - __half2float(hb));
    }
}

__global__ void zero_state(float* f, float* c0, __half* htl, int n)
{
    int i = blockIdx.x * blockDim.x + threadIdx.x;
    if (i >= n) return;
    f[i] = 0.f;
    c0[i] = 0.f;
    htl[i] = __float2half_rn(0.f);
    htl[i + n] = __float2half_rn(0.f);
}

// ---------------- host orchestration ----------------
extern "C" void kernel_launch(void* const* d_in, const int* in_sizes, int n_in,
                              void* d_out, int out_size)
{
    const int s = (in_sizes[3] == 1) ? 1 : 0;

    const int*   input_var  = (const int*)  d_in[0];
    const float* input_mask = (const float*)d_in[1];
    const int*   target_var = (const int*)  d_in[2];
    const float* embedding  = (const float*)d_in[3 + s];
    const float* attn_w     = (const float*)d_in[4 + s];
    const float* attn_b     = (const float*)d_in[5 + s];
    const float* set_Wih    = (const float*)d_in[6 + s];
    const float* set_bih    = (const float*)d_in[8 + s];
    const float* set_bhh    = (const float*)d_in[9 + s];
    const float* gen_Whh    = (const float*)d_in[14 + s];
    const float* gen_bih    = (const float*)d_in[15 + s];
    const float* gen_bhh    = (const float*)d_in[16 + s];
    const float* gen_outW   = (const float*)d_in[17 + s];
    const float* gen_outb   = (const float*)d_in[18 + s];
    const float* menc_Wih   = (const float*)d_in[19 + s];
    const float* menc_Whh   = (const float*)d_in[20 + s];
    const float* menc_bih   = (const float*)d_in[21 + s];
    const float* menc_bhh   = (const float*)d_in[22 + s];
    const float* dec_Wih    = (const float*)d_in[25 + s];
    const float* dec_Whh    = (const float*)d_in[26 + s];
    const float* dec_bih    = (const float*)d_in[27 + s];
    const float* dec_bhh    = (const float*)d_in[28 + s];
    const float* dec_outW   = (const float*)d_in[29 + s];
    const float* dec_outb   = (const float*)d_in[30 + s];
    float* out = (float*)d_out;

    float *c, *mm, *m, *hA32, *hB32, *pbs, *pbg, *pbm, *pbd, *pgm, *ptab;
    cudaGetSymbolAddress((void**)&c,    d_c);
    cudaGetSymbolAddress((void**)&mm,   d_mm);
    cudaGetSymbolAddress((void**)&m,    d_m);
    cudaGetSymbolAddress((void**)&hA32, d_hA32);
    cudaGetSymbolAddress((void**)&hB32, d_hB32);
    cudaGetSymbolAddress((void**)&pbs, pb_set);  cudaGetSymbolAddress((void**)&pbg, pb_gen);
    cudaGetSymbolAddress((void**)&pbm, pb_menc); cudaGetSymbolAddress((void**)&pbd, pb_dec);
    cudaGetSymbolAddress((void**)&pgm, pg_menc); cudaGetSymbolAddress((void**)&ptab, d_ptab);
    __half *etl, *wstl, *wgtl, *wmitl, *wmhtl, *wditl, *wdhtl, *wotl;
    __half *hAt, *hBt, *rt, *mstl, *hallt;
    cudaGetSymbolAddress((void**)&etl,   e_tl);
    cudaGetSymbolAddress((void**)&wstl,  wset_tl);
    cudaGetSymbolAddress((void**)&wgtl,  wgen_tl);
    cudaGetSymbolAddress((void**)&wmitl, wmi_tl);
    cudaGetSymbolAddress((void**)&wmhtl, wmh_tl);
    cudaGetSymbolAddress((void**)&wditl, wdi_tl);
    cudaGetSymbolAddress((void**)&wdhtl, wdh_tl);
    cudaGetSymbolAddress((void**)&wotl,  wo_tl);
    cudaGetSymbolAddress((void**)&hAt,   hA_tl);
    cudaGetSymbolAddress((void**)&hBt,   hB_tl);
    cudaGetSymbolAddress((void**)&rt,    r_tl);
    cudaGetSymbolAddress((void**)&mstl,  msg_tl);
    cudaGetSymbolAddress((void**)&hallt, hall_tl);

    cudaFuncSetAttribute(gemm_tc1,  cudaFuncAttributeMaxDynamicSharedMemorySize, SMEM_N1);
    cudaFuncSetAttribute(gen_loop,  cudaFuncAttributeMaxDynamicSharedMemorySize, SMEM_P);
    cudaFuncSetAttribute(menc_loop, cudaFuncAttributeMaxDynamicSharedMemorySize, SMEM_P);
    cudaFuncSetAttribute(dec_loop,  cudaFuncAttributeMaxDynamicSharedMemorySize, SMEM_P);

    const dim3 pg(32, 8);                        // persistent grid: 256 CTAs
    const int  cb = (Bsz * Hd) / 256;

    // L0: both gen-phase weight conversions fused
    conv_pair_perm<<<(2 * G4H * Hd + 255) / 256, 256>>>(set_Wih, wstl, gen_Whh, wgtl);
    // L1: attention + all bias preps + m fill fused
    prep_attn<<<Bsz + (4 * G4H + Bsz + 255) / 256, 256>>>(
        input_var, input_mask, embedding, attn_w, attn_b, rt,
        set_bih, set_bhh, pbs, gen_bih, gen_bhh, pbg,
        menc_bih, menc_bhh, pbm, dec_bih, dec_bhh, pbd, m);
    // L2: set encoder cell
    gemm_tc1<<<dim3(32, 4), 256, SMEM_N1>>>(nullptr, G4H, rt, 0, wstl, 16, pbs,
                                            1, c, hA32, hAt);
    // L3: gen persistent loop (ncu target)
    gen_loop<<<pg, 256, SMEM_P>>>(wgtl, pbg, gen_outW, gen_outb, c, mm, m,
                                  hAt, hBt, hA32, hB32, mstl);

    // ---- menc phase ----
    conv_perm_tl<<<(G4H * MVd + 255) / 256, 256>>>(menc_Wih, wmitl, MVd);
    conv_perm_tl<<<(G4H * Hd + 255) / 256, 256>>>(menc_Whh, wmhtl, Hd);
    gemm_tc1<<<dim3(32, (Ld * Bsz) / 128), 256, SMEM_N1>>>(pgm, G4H, mstl, 0,
                                                           wmitl, 1, pbm, 0,
                                                           nullptr, nullptr, nullptr);
    zero_state<<<cb, 256>>>(hA32, c, hAt, Bsz * Hd);
    menc_loop<<<pg, 256, SMEM_P>>>(wmhtl, pgm, c, mm, hAt, hBt, hA32, hB32);
    // Ld = 30 even -> final menc h tiled in hAt

    // ---- dec phase: vocab-factorized input gates ----
    conv_pair_perm<<<(2 * G4H * Hd + 255) / 256, 256>>>(dec_Wih, wditl, dec_Whh, wdhtl);
    conv_tl<<<(Vb * Hd + 255) / 256, 256>>>(embedding, etl, Vb, Hd);
    gemm_tc1<<<dim3(32, Vb / 128), 256, SMEM_N1>>>(ptab, G4H, etl, 0,
                                                   wditl, 16, pbd, 0,
                                                   nullptr, nullptr, nullptr);
    dec_loop<<<pg, 256, SMEM_P>>>(wdhtl, ptab, target_var, c, hAt, hallt);

    // ---- logits (1-product fp16) ----
    conv_tl<<<(Vb * Hd + 255) / 256, 256>>>(dec_outW, wotl, Vb, Hd);
    gemm_tc1<<<dim3(Vb / 128, (Tln * Bsz) / 128), 256, SMEM_N1>>>(
        out, Vb, hallt, 0, wotl, 16, dec_outb, 0, nullptr, nullptr, nullptr);
}

// round 14
// speedup vs baseline: 1.2669x; 1.2669x over previous
#include <cuda_runtime.h>
#include <cuda_fp16.h>
#include <cstdint>

// ---------------- problem constants ----------------
#define Bsz 512
#define Wln 50
#define Tln 50
#define Hd  1024
#define Vb  1024
#define MVd 64
#define Ld  30
#define G4H 4096
#define SOS_INDEX 0
#define EOS_INDEX 1

#define PLANE_B 16384
#define BLKB    32768
#define BLKE    16384
#define GRID_N  256

// ---------------- scratch ----------------
__device__ float d_c   [Bsz * Hd];
__device__ float d_mm  [Ld * Bsz];
__device__ float d_m   [Bsz];
__device__ float d_hA32[Bsz * Hd];
__device__ float d_hB32[Bsz * Hd];
__device__ float pb_set[G4H], pb_gen[G4H], pb_menc[G4H], pb_dec[G4H];
__device__ unsigned g_cnt, g_epoch;
__device__ float pg_menc[Ld * Bsz * G4H];
__device__ float d_ptab [Vb * G4H];

#define TLA __align__(1024)
__device__ TLA __half e_tl   [128 * BLKE];
__device__ TLA __half wset_tl[512 * BLKE];
__device__ TLA __half wgen_tl[512 * BLKE];
__device__ TLA __half wmi_tl [32  * BLKE];
__device__ TLA __half wmh_tl [512 * BLKE];
__device__ TLA __half wdi_tl [512 * BLKE];
__device__ TLA __half wdh_tl [512 * BLKE];
__device__ TLA __half wo_tl  [128 * BLKE];
__device__ TLA __half hA_tl  [64  * BLKE];
__device__ TLA __half hB_tl  [64  * BLKE];
__device__ TLA __half r_tl   [64  * BLKE];
__device__ TLA __half msg_tl [Ld * 4 * BLKE];
__device__ TLA __half hall_tl[Tln * 64 * BLKE];

// ---------------- ptx helpers ----------------
__device__ __forceinline__ uint32_t smem_to_u32(const void* p) {
    uint32_t a;
    asm("{ .reg .u64 t; cvta.to.shared.u64 t, %1; cvt.u32.u64 %0, t; }" : "=r"(a) : "l"(p));
    return a;
}
#define CP_ASYNC16(dst, src) \
    asm volatile("cp.async.cg.shared.global [%0], [%1], 16;" :: "r"(dst), "l"(src))
#define CP_COMMIT() asm volatile("cp.async.commit_group;" ::: "memory")
#define CP_WAIT0()  asm volatile("cp.async.wait_group 0;" ::: "memory")
#define CP_WAIT1()  asm volatile("cp.async.wait_group 1;" ::: "memory")
#define LDSM4(r, a) \
    asm volatile("ldmatrix.sync.aligned.m8n8.x4.shared.b16 {%0,%1,%2,%3}, [%4];" \
        : "=r"((r)[0]), "=r"((r)[1]), "=r"((r)[2]), "=r"((r)[3]) : "r"(a))
#define SWZ(x) ((x) ^ (((x) >> 3) & 0x70))

__device__ __forceinline__ void mma_f16(float* c, const uint32_t* a, const uint32_t* b)
{
    asm volatile(
        "mma.sync.aligned.m16n8k16.row.col.f32.f16.f16.f32 "
        "{%0,%1,%2,%3}, {%4,%5,%6,%7}, {%8,%9}, {%0,%1,%2,%3};\n"
        : "+f"(c[0]), "+f"(c[1]), "+f"(c[2]), "+f"(c[3])
        : "r"(a[0]), "r"(a[1]), "r"(a[2]), "r"(a[3]), "r"(b[0]), "r"(b[1]));
}

__device__ __forceinline__ size_t tlo(int row, int kelem, int KB)
{
    return ((size_t)(row >> 7) * KB + (kelem >> 6)) * BLKB +
           (size_t)SWZ((uint32_t)(((row & 127) << 7) | ((kelem & 63) << 1)));
}

// ---------------- smem layout ----------------
#define SM_TILES  1024
#define NSTAGE    3
#define SGPAD     129
#define STAGE64_B 24576
#define SMEM_P    (SM_TILES + NSTAGE * STAGE64_B)
#define SMEM_N1   (SM_TILES + NSTAGE * 2 * PLANE_B)

// ---------------- grid barrier ----------------
__device__ __forceinline__ void gbar(unsigned& tgt)
{
    __syncthreads();
    if (threadIdx.x == 0) {
        __threadfence();
        unsigned v = atomicAdd(&g_cnt, 1u);
        if ((v & (GRID_N - 1)) == (GRID_N - 1)) {
            __threadfence();
            atomicAdd(&g_epoch, 1u);
        } else {
            unsigned e;
            do {
                asm volatile("ld.acquire.gpu.global.u32 %0, [%1];"
                             : "=r"(e) : "l"(&g_epoch));
            } while ((int)(e - tgt) < 0);
        }
        __threadfence();
    }
    __syncthreads();
    tgt++;
}

// ---------------- 64x128 1-product GEMM mainloop -----------------------------
__device__ __forceinline__ void gemm_part64(
    float (&acc)[2][4][4], uint32_t sb,
    const char* __restrict__ atl, int ablk,
    const char* __restrict__ wtl, int KB,
    int bm, int bn, int tid)
{
    __syncthreads();
    const uint32_t ahalf = ((uint32_t)(bm >> 6) & 1u) * 8192u;
    auto issue = [&](int kb) {
        const uint32_t stage = sb + SM_TILES + (kb % NSTAGE) * STAGE64_B;
        const char* asrc = atl + ((size_t)(ablk + (bm >> 7) * KB + kb)) * BLKB + ahalf;
        const char* wsrc = wtl + ((size_t)((bn >> 7) * KB + kb)) * BLKB;
        uint32_t ao = (uint32_t)tid * 32;
        CP_ASYNC16(stage + ao,      asrc + ao);
        CP_ASYNC16(stage + ao + 16, asrc + ao + 16);
        uint32_t wo = (uint32_t)tid * 64;
        #pragma unroll
        for (int j = 0; j < 4; j++)
            CP_ASYNC16(stage + 8192 + wo + j * 16, wsrc + wo + j * 16);
        CP_COMMIT();
    };
    issue(0);
    if (KB > 1) issue(1);
    const int wid = tid >> 5, lane = tid & 31;
    const int wm = (wid >> 2) * 32, wn = (wid & 3) * 32;
    for (int kb = 0; kb < KB; kb++) {
        if (kb + 1 < KB) { CP_WAIT1(); } else { CP_WAIT0(); }
        __syncthreads();
        if (kb + 2 < KB) issue(kb + 2);
        const uint32_t stage = sb + SM_TILES + (kb % NSTAGE) * STAGE64_B;
        #pragma unroll
        for (int ks = 0; ks < 4; ks++) {
            uint32_t ah[2][4], bh[4][2];
            {
                const int arow = wm + (lane & 15);
                const int acol = ks * 32 + ((lane >> 4) << 4);
                #pragma unroll
                for (int mt = 0; mt < 2; mt++) {
                    uint32_t off = SWZ((uint32_t)((arow + mt * 16) * 128 + acol));
                    LDSM4(ah[mt], stage + off);
                }
            }
            {
                const int brow = wn + (lane & 7) + ((lane >> 4) << 3);
                const int bcol = ks * 32 + (((lane >> 3) & 1) << 4);
                #pragma unroll
                for (int p2 = 0; p2 < 2; p2++) {
                    uint32_t off = SWZ((uint32_t)((brow + p2 * 16) * 128 + bcol));
                    uint32_t r[4];
                    LDSM4(r, stage + 8192 + off);
                    bh[p2 * 2][0] = r[0]; bh[p2 * 2][1] = r[1];
                    bh[p2 * 2 + 1][0] = r[2]; bh[p2 * 2 + 1][1] = r[3];
                }
            }
            #pragma unroll
            for (int mt = 0; mt < 2; mt++)
                #pragma unroll
                for (int nt = 0; nt < 4; nt++)
                    mma_f16(acc[mt][nt], ah[mt], bh[nt]);
        }
    }
}

// ---------------- 64-row fused LSTM epilogue (hi plane only) -----------------
__device__ __forceinline__ void lstm_epi64(
    float (&acc)[2][4][4], char* smem,
    const float* __restrict__ bias, const float* __restrict__ pg,
    const float* __restrict__ ptab, const int* __restrict__ gidx,
    const float* __restrict__ c_in, float* __restrict__ c_out,
    float* __restrict__ h_f32, char* __restrict__ ht,
    const float* __restrict__ maskp, const float* __restrict__ h_old,
    int bm, int bn, int tid)
{
    const int wid = tid >> 5, lane = tid & 31;
    const int wm = (wid >> 2) * 32, wn = (wid & 3) * 32;
    const bool use_pg = (pg != nullptr) || (ptab != nullptr);
    __syncthreads();
    float* sg = (float*)(smem + SM_TILES);
    #pragma unroll
    for (int nt = 0; nt < 4; nt++) {
        const int ln = wn + nt * 8 + 2 * (lane & 3);
        const float bias0 = use_pg ? 0.f : bias[bn + ln];
        const float bias1 = use_pg ? 0.f : bias[bn + ln + 1];
        #pragma unroll
        for (int mt = 0; mt < 2; mt++) {
            const int lm = wm + mt * 16 + (lane >> 2);
            sg[lm * SGPAD + ln]           = acc[mt][nt][0] + bias0;
            sg[lm * SGPAD + ln + 1]       = acc[mt][nt][1] + bias1;
            sg[(lm + 8) * SGPAD + ln]     = acc[mt][nt][2] + bias0;
            sg[(lm + 8) * SGPAD + ln + 1] = acc[mt][nt][3] + bias1;
        }
    }
    __syncthreads();

    const int gu_base = bn >> 2;
    for (int i = tid; i < 64 * 32; i += 256) {
        const int u = i & 31, mrow = i >> 5;
        const float* row = sg + mrow * SGPAD + u * 4;
        float gi_ = row[0], gf_ = row[1], gg_ = row[2], go_ = row[3];
        const int gm = bm + mrow;
        const int ug = gu_base + u;
        if (ptab) {
            int rid = gidx ? gidx[gm] : SOS_INDEX;
            float4 pv = *(const float4*)(ptab + (size_t)rid * G4H + ug * 4);
            gi_ += pv.x; gf_ += pv.y; gg_ += pv.z; go_ += pv.w;
        } else if (pg) {
            float4 pv = *(const float4*)(pg + (size_t)gm * G4H + ug * 4);
            gi_ += pv.x; gf_ += pv.y; gg_ += pv.z; go_ += pv.w;
        }
        const size_t ci = (size_t)gm * Hd + ug;
        float cold = c_in ? c_in[ci] : 0.f;
        float si = 1.f / (1.f + expf(-gi_));
        float sf = 1.f / (1.f + expf(-gf_));
        float so = 1.f / (1.f + expf(-go_));
        float cn = sf * cold + si * tanhf(gg_);
        float hn = so * tanhf(cn);
        if (maskp) {
            float mt_ = maskp[gm];
            hn = mt_ * hn + (1.f - mt_) * h_old[ci];
            cn = mt_ * cn + (1.f - mt_) * cold;
        }
        c_out[ci] = cn;
        if (h_f32) h_f32[ci] = hn;
        *(__half*)(ht + tlo(gm, ug, 16)) = __float2half_rn(hn);
    }
}

// ---------------- in-kernel gen output head (2 rows per CTA, 256 CTAs) -------
__device__ __forceinline__ void gen_out_phase(
    char* smem, const float* __restrict__ qf,
    const float* __restrict__ outW, const float* __restrict__ outb,
    char* __restrict__ msg_l, float* __restrict__ mm_l, float* __restrict__ m_state,
    int cta, int tid)
{
    float* hs  = (float*)(smem + SM_TILES);
    float* red = (float*)(smem + SM_TILES + 8192);
    const int slot = tid >> 6, j = tid & 63;
    const int row = cta * 2 + slot;
    if (slot < 2)
        for (int k = j; k < Hd; k += 64)
            hs[slot * Hd + k] = qf[(size_t)row * Hd + k];
    __syncthreads();

    if (slot < 2) {
        float acc = outb[j];
        const float4* h4 = (const float4*)(hs + slot * Hd);
        const float4* w4 = (const float4*)(outW + (size_t)j * Hd);
        #pragma unroll 4
        for (int k = 0; k < Hd / 4; k++) {
            float4 wv = w4[k], hv = h4[k];
            acc += wv.x * hv.x + wv.y * hv.y + wv.z * hv.z + wv.w * hv.w;
        }
        float vmax = acc;
        #pragma unroll
        for (int o = 16; o; o >>= 1) vmax = fmaxf(vmax, __shfl_xor_sync(0xffffffffu, vmax, o));
        if ((j & 31) == 0) red[slot * 2 + (j >> 5)] = vmax;
        __syncwarp();
        __syncthreads();
        vmax = fmaxf(red[slot * 2], red[slot * 2 + 1]);
        float e = expf(acc - vmax);
        float ssum = e;
        #pragma unroll
        for (int o = 16; o; o >>= 1) ssum += __shfl_xor_sync(0xffffffffu, ssum, o);
        __syncthreads();
        if ((j & 31) == 0) red[slot * 2 + (j >> 5)] = ssum;
        __syncthreads();
        ssum = red[slot * 2] + red[slot * 2 + 1];
        float p = e / ssum;
        *(__half*)(msg_l + tlo(row, j, 1)) = __float2half_rn(p);
        if (j == EOS_INDEX) {
            float mo = m_state[row];
            mm_l[row] = mo;
            m_state[row] = mo * (1.f - p);
        }
    } else {
        __syncthreads();
        __syncthreads();
        __syncthreads();
    }
}

#define ZERO_ACC2(acc) { \
    _Pragma("unroll") for (int mt = 0; mt < 2; mt++) \
    _Pragma("unroll") for (int nt = 0; nt < 4; nt++) \
    _Pragma("unroll") for (int i = 0; i < 4; i++) acc[mt][nt][i] = 0.f; }
#define ZERO_ACC4(acc) { \
    _Pragma("unroll") for (int mt = 0; mt < 4; mt++) \
    _Pragma("unroll") for (int nt = 0; nt < 4; nt++) \
    _Pragma("unroll") for (int i = 0; i < 4; i++) acc[mt][nt][i] = 0.f; }

// ---------------- persistent loop kernels ------------------------------------
__global__ void __launch_bounds__(256, 2)
gen_loop(const __half* __restrict__ wg, const float* __restrict__ bias,
         const float* __restrict__ outW, const float* __restrict__ outb,
         float* c, float* mm, float* m,
         __half* hA, __half* hB, float* fA, float* fB, __half* msg)
{
    extern __shared__ char smem[];
    const uint32_t sb = smem_to_u32(smem);
    const int tid = threadIdx.x;
    const int bm = blockIdx.y * 64, bn = blockIdx.x * 128;
    const int cta = blockIdx.y * 32 + blockIdx.x;
    unsigned tgt = *((volatile unsigned*)&g_epoch) + 1;
    const char* pt = (const char*)hA;
    char* qt = (char*)hB;
    float* qf = fB;
    float* of = fA;
    float acc[2][4][4];
    for (int l = 0; l < Ld; l++) {
        ZERO_ACC2(acc);
        gemm_part64(acc, sb, pt, 0, (const char*)wg, 16, bm, bn, tid);
        lstm_epi64(acc, smem, bias, nullptr, nullptr, nullptr,
                   c, c, qf, qt, nullptr, nullptr, bm, bn, tid);
        gbar(tgt);
        gen_out_phase(smem, qf, outW, outb,
                      (char*)msg + (size_t)l * 4 * BLKB, mm + l * Bsz, m, cta, tid);
        { const char* t = pt; pt = qt; qt = (char*)t; }
        { float* t = qf; qf = of; of = t; }
    }
}

__global__ void __launch_bounds__(256, 2)
menc_loop(const __half* __restrict__ wmh, const float* __restrict__ pgm,
          float* c, const float* __restrict__ mm,
          __half* hA, __half* hB, float* fA, float* fB)
{
    extern __shared__ char smem[];
    const uint32_t sb = smem_to_u32(smem);
    const int tid = threadIdx.x;
    const int bm = blockIdx.y * 64, bn = blockIdx.x * 128;
    unsigned tgt = *((volatile unsigned*)&g_epoch) + 1;
    const char* pt = (const char*)hA;
    char* qt = (char*)hB;
    const float* pf = fA;
    float* qf = fB;
    float acc[2][4][4];
    for (int l = 0; l < Ld; l++) {
        ZERO_ACC2(acc);
        gbar(tgt);
        gemm_part64(acc, sb, pt, 0, (const char*)wmh, 16, bm, bn, tid);
        lstm_epi64(acc, smem, nullptr, pgm + (size_t)l * Bsz * G4H, nullptr, nullptr,
                   c, c, qf, qt, mm + l * Bsz, pf, bm, bn, tid);
        { const char* t = pt; pt = qt; qt = (char*)t; }
        { const float* t = pf; pf = qf; qf = (float*)t; }
    }
}

__global__ void __launch_bounds__(256, 2)
dec_loop(const __half* __restrict__ wdh, const float* __restrict__ ptab,
         const int* __restrict__ tgt_var,
         float* c, const __half* __restrict__ h0t, __half* hallt)
{
    extern __shared__ char smem[];
    const uint32_t sb = smem_to_u32(smem);
    const int tid = threadIdx.x;
    const int bm = blockIdx.y * 64, bn = blockIdx.x * 128;
    unsigned tgt = *((volatile unsigned*)&g_epoch) + 1;
    float acc[2][4][4];
    for (int t = 0; t < Tln; t++) {
        ZERO_ACC2(acc);
        gbar(tgt);
        const char* a2 = (t == 0) ? (const char*)h0t : (const char*)hallt;
        int ab = (t == 0) ? 0 : (t - 1) * 64;
        gemm_part64(acc, sb, a2, ab, (const char*)wdh, 16, bm, bn, tid);
        const int* gidx = (t == 0) ? nullptr : (tgt_var + (size_t)(t - 1) * Bsz);
        lstm_epi64(acc, smem, nullptr, nullptr, ptab, gidx,
                   c, c, nullptr,
                   (char*)hallt + (size_t)t * 64 * BLKB, nullptr, nullptr, bm, bn, tid);
    }
}

// ---------------- standalone GEMM kernel (1-product, 128x128 tiles) ----------
__global__ void __launch_bounds__(256, 2)
gemm_tc1(float* __restrict__ C, int N,
         const __half* __restrict__ a1, int a1base,
         const __half* __restrict__ w1, int KB1,
         const float* __restrict__ bias, int mode,
         float* __restrict__ c_out, float* __restrict__ h_f32,
         __half* __restrict__ ht_out)
{
    extern __shared__ char smem[];
    const uint32_t sb = smem_to_u32(smem);
    const int bm = blockIdx.y * 128, bn = blockIdx.x * 128;
    const int tid = threadIdx.x, wid = tid >> 5, lane = tid & 31;
    const int wm = (wid >> 2) * 64;
    const int wn = (wid & 3) * 32;
    const int nb = KB1;

    auto issue = [&](int kb) {
        const uint32_t stage = sb + SM_TILES + (kb % NSTAGE) * (2 * PLANE_B);
        const char* asrc = (const char*)a1 + ((size_t)(a1base + (bm >> 7) * KB1 + kb)) * BLKB;
        const char* wsrc = (const char*)w1 + ((size_t)((bn >> 7) * KB1 + kb)) * BLKB;
        #pragma unroll
        for (int j = 0; j < 4; j++) {
            uint32_t off = (uint32_t)(tid * 4 + j) * 16;
            CP_ASYNC16(stage + off, asrc + off);
            CP_ASYNC16(stage + PLANE_B + off, wsrc + off);
        }
        CP_COMMIT();
    };

    float acc[4][4][4];
    ZERO_ACC4(acc);

    issue(0);
    if (nb > 1) issue(1);

    for (int kb = 0; kb < nb; kb++) {
        if (kb + 1 < nb) { CP_WAIT1(); } else { CP_WAIT0(); }
        __syncthreads();
        if (kb + 2 < nb) issue(kb + 2);
        const uint32_t stage = sb + SM_TILES + (kb % NSTAGE) * (2 * PLANE_B);

        #pragma unroll
        for (int ks = 0; ks < 4; ks++) {
            uint32_t ah[4][4], bh[4][2];
            {
                const int arow = wm + (lane & 15);
                const int acol = ks * 32 + ((lane >> 4) << 4);
                #pragma unroll
                for (int mt = 0; mt < 4; mt++) {
                    uint32_t off = SWZ((uint32_t)((arow + mt * 16) * 128 + acol));
                    LDSM4(ah[mt], stage + off);
                }
            }
            {
                const int brow = wn + (lane & 7) + ((lane >> 4) << 3);
                const int bcol = ks * 32 + (((lane >> 3) & 1) << 4);
                #pragma unroll
                for (int p2 = 0; p2 < 2; p2++) {
                    uint32_t off = SWZ((uint32_t)((brow + p2 * 16) * 128 + bcol));
                    uint32_t r[4];
                    LDSM4(r, stage + PLANE_B + off);
                    bh[p2 * 2][0] = r[0]; bh[p2 * 2][1] = r[1];
                    bh[p2 * 2 + 1][0] = r[2]; bh[p2 * 2 + 1][1] = r[3];
                }
            }
            #pragma unroll
            for (int mt = 0; mt < 4; mt++)
                #pragma unroll
                for (int nt = 0; nt < 4; nt++)
                    mma_f16(acc[mt][nt], ah[mt], bh[nt]);
        }
    }

    if (mode == 0) {
        #pragma unroll
        for (int nt = 0; nt < 4; nt++) {
            const int n0 = bn + wn + nt * 8 + 2 * (lane & 3);
            float bias0 = bias ? bias[n0] : 0.f;
            float bias1 = bias ? bias[n0 + 1] : 0.f;
            #pragma unroll
            for (int mt = 0; mt < 4; mt++) {
                const int m0 = bm + wm + mt * 16 + (lane >> 2);
                float2 v0 = make_float2(acc[mt][nt][0] + bias0, acc[mt][nt][1] + bias1);
                float2 v1 = make_float2(acc[mt][nt][2] + bias0, acc[mt][nt][3] + bias1);
                *(float2*)&C[(size_t)m0 * N + n0] = v0;
                *(float2*)&C[(size_t)(m0 + 8) * N + n0] = v1;
            }
        }
        return;
    }

    // 128-row fused LSTM epilogue (set encoder; c_in == 0)
    __syncthreads();
    float* sg = (float*)(smem + SM_TILES);
    #pragma unroll
    for (int nt = 0; nt < 4; nt++) {
        const int ln = wn + nt * 8 + 2 * (lane & 3);
        const float bias0 = bias[bn + ln];
        const float bias1 = bias[bn + ln + 1];
        #pragma unroll
        for (int mt = 0; mt < 4; mt++) {
            const int lm = wm + mt * 16 + (lane >> 2);
            sg[lm * SGPAD + ln]           = acc[mt][nt][0] + bias0;
            sg[lm * SGPAD + ln + 1]       = acc[mt][nt][1] + bias1;
            sg[(lm + 8) * SGPAD + ln]     = acc[mt][nt][2] + bias0;
            sg[(lm + 8) * SGPAD + ln + 1] = acc[mt][nt][3] + bias1;
        }
    }
    __syncthreads();
    const int gu_base = bn >> 2;
    char* ht = (char*)ht_out;
    for (int i = tid; i < 128 * 32; i += 256) {
        const int u = i & 31, mrow = i >> 5;
        const float* row = sg + mrow * SGPAD + u * 4;
        float gi_ = row[0], gg_ = row[2], go_ = row[3];
        const int gm = bm + mrow;
        const int ug = gu_base + u;
        const size_t ci = (size_t)gm * Hd + ug;
        float si = 1.f / (1.f + expf(-gi_));
        float so = 1.f / (1.f + expf(-go_));
        float cn = si * tanhf(gg_);
        float hn = so * tanhf(cn);
        c_out[ci] = cn;
        if (h_f32) h_f32[ci] = hn;
        *(__half*)(ht + tlo(gm, ug, 16)) = __float2half_rn(hn);
    }
}

// ---------------- conversion / pre-tiling kernels (hi plane only) -----------
__device__ __forceinline__ void conv_perm_one(const float* s, __half* dst, int K, int i)
{
    int np = i / K, k = i - np * K;
    int u = np >> 2, g = np & 3;
    float x = s[(size_t)(g * Hd + u) * K + k];
    *(__half*)((char*)dst + tlo(np, k, K >> 6)) = __float2half_rn(x);
}

__global__ void conv_perm_tl(const float* __restrict__ s, __half* __restrict__ dst, int K)
{
    int i = blockIdx.x * blockDim.x + threadIdx.x;
    if (i >= G4H * K) return;
    conv_perm_one(s, dst, K, i);
}

__global__ void conv_pair_perm(const float* __restrict__ s0, __half* __restrict__ d0,
                               const float* __restrict__ s1, __half* __restrict__ d1)
{
    int i = blockIdx.x * blockDim.x + threadIdx.x;
    if (i < G4H * Hd) conv_perm_one(s0, d0, Hd, i);
    else if (i < 2 * G4H * Hd) conv_perm_one(s1, d1, Hd, i - G4H * Hd);
}

__global__ void conv_tl(const float* __restrict__ s, __half* __restrict__ dst,
                        int rows, int K)
{
    int i = blockIdx.x * blockDim.x + threadIdx.x;
    if (i >= rows * K) return;
    int np = i / K, k = i - np * K;
    *(__half*)((char*)dst + tlo(np, k, K >> 6)) = __float2half_rn(s[(size_t)np * K + k]);
}

// fused: attention (blocks 0..511) + bias prep / m fill (blocks 512+)
__global__ void prep_attn(const int* __restrict__ inp, const float* __restrict__ mask,
                          const float* __restrict__ emb, const float* __restrict__ attn_w,
                          const float* __restrict__ attn_b, __half* __restrict__ rtl,
                          const float* sb1, const float* sb2, float* so,
                          const float* gb1, const float* gb2, float* go,
                          const float* mb1, const float* mb2, float* mo,
                          const float* db1, const float* db2, float* dopt,
                          float* m)
{
    __shared__ float aw[Wln];
    __shared__ int   idxs[Wln];
    const int tid = threadIdx.x;

    if (blockIdx.x >= Bsz) {
        int i = (blockIdx.x - Bsz) * 256 + tid;
        if (i < 4 * G4H) {
            int set = i >> 12, np = i & (G4H - 1);
            int u = np >> 2, g = np & 3;
            int src = g * Hd + u;
            float v; float* o;
            if (set == 0)      { v = sb1[src] + sb2[src]; o = so; }
            else if (set == 1) { v = gb1[src] + gb2[src]; o = go; }
            else if (set == 2) { v = mb1[src] + mb2[src]; o = mo; }
            else               { v = db1[src] + db2[src]; o = dopt; }
            o[np] = v;
        } else if (i < 4 * G4H + Bsz) {
            m[i - 4 * G4H] = 1.f;
        }
        return;
    }

    const int b = blockIdx.x;
    const int lane = tid & 31, wrp = tid >> 5;
    if (tid < Wln) idxs[tid] = inp[b * Wln + tid];
    __syncthreads();
    const float* w2 = attn_w + Hd;
    for (int wi = wrp; wi < Wln; wi += 8) {
        const float* e = emb + (size_t)idxs[wi] * Hd;
        float acc = 0.f;
        for (int k = lane; k < Hd; k += 32) acc += e[k] * w2[k];
        #pragma unroll
        for (int o = 16; o; o >>= 1) acc += __shfl_xor_sync(0xffffffffu, acc, o);
        if (lane == 0) {
            float a = 1.f / (1.f + expf(-(acc + attn_b[0])));
            aw[wi] = a * mask[wi * Bsz + b];
        }
    }
    __syncthreads();
    char* d = (char*)rtl;
    for (int hh = tid; hh < Hd; hh += 256) {
        float acc = 0.f;
        #pragma unroll 5
        for (int wi = 0; wi < Wln; wi++)
            acc += aw[wi] * emb[(size_t)idxs[wi] * Hd + hh];
        *(__half*)(d + tlo(b, hh, 16)) = __float2half_rn(acc);
    }
}

__global__ void zero_state(float* f, float* c0, __half* htl, int n)
{
    int i = blockIdx.x * blockDim.x + threadIdx.x;
    if (i >= n) return;
    f[i] = 0.f;
    c0[i] = 0.f;
    htl[i] = __float2half_rn(0.f);   // hi plane region covers [0, n)
}

// ---------------- host orchestration ----------------
extern "C" void kernel_launch(void* const* d_in, const int* in_sizes, int n_in,
                              void* d_out, int out_size)
{
    const int s = (in_sizes[3] == 1) ? 1 : 0;

    const int*   input_var  = (const int*)  d_in[0];
    const float* input_mask = (const float*)d_in[1];
    const int*   target_var = (const int*)  d_in[2];
    const float* embedding  = (const float*)d_in[3 + s];
    const float* attn_w     = (const float*)d_in[4 + s];
    const float* attn_b     = (const float*)d_in[5 + s];
    const float* set_Wih    = (const float*)d_in[6 + s];
    const float* set_bih    = (const float*)d_in[8 + s];
    const float* set_bhh    = (const float*)d_in[9 + s];
    const float* gen_Whh    = (const float*)d_in[14 + s];
    const float* gen_bih    = (const float*)d_in[15 + s];
    const float* gen_bhh    = (const float*)d_in[16 + s];
    const float* gen_outW   = (const float*)d_in[17 + s];
    const float* gen_outb   = (const float*)d_in[18 + s];
    const float* menc_Wih   = (const float*)d_in[19 + s];
    const float* menc_Whh   = (const float*)d_in[20 + s];
    const float* menc_bih   = (const float*)d_in[21 + s];
    const float* menc_bhh   = (const float*)d_in[22 + s];
    const float* dec_Wih    = (const float*)d_in[25 + s];
    const float* dec_Whh    = (const float*)d_in[26 + s];
    const float* dec_bih    = (const float*)d_in[27 + s];
    const float* dec_bhh    = (const float*)d_in[28 + s];
    const float* dec_outW   = (const float*)d_in[29 + s];
    const float* dec_outb   = (const float*)d_in[30 + s];
    float* out = (float*)d_out;

    float *c, *mm, *m, *hA32, *hB32, *pbs, *pbg, *pbm, *pbd, *pgm, *ptab;
    cudaGetSymbolAddress((void**)&c,    d_c);
    cudaGetSymbolAddress((void**)&mm,   d_mm);
    cudaGetSymbolAddress((void**)&m,    d_m);
    cudaGetSymbolAddress((void**)&hA32, d_hA32);
    cudaGetSymbolAddress((void**)&hB32, d_hB32);
    cudaGetSymbolAddress((void**)&pbs, pb_set);  cudaGetSymbolAddress((void**)&pbg, pb_gen);
    cudaGetSymbolAddress((void**)&pbm, pb_menc); cudaGetSymbolAddress((void**)&pbd, pb_dec);
    cudaGetSymbolAddress((void**)&pgm, pg_menc); cudaGetSymbolAddress((void**)&ptab, d_ptab);
    __half *etl, *wstl, *wgtl, *wmitl, *wmhtl, *wditl, *wdhtl, *wotl;
    __half *hAt, *hBt, *rt, *mstl, *hallt;
    cudaGetSymbolAddress((void**)&etl,   e_tl);
    cudaGetSymbolAddress((void**)&wstl,  wset_tl);
    cudaGetSymbolAddress((void**)&wgtl,  wgen_tl);
    cudaGetSymbolAddress((void**)&wmitl, wmi_tl);
    cudaGetSymbolAddress((void**)&wmhtl, wmh_tl);
    cudaGetSymbolAddress((void**)&wditl, wdi_tl);
    cudaGetSymbolAddress((void**)&wdhtl, wdh_tl);
    cudaGetSymbolAddress((void**)&wotl,  wo_tl);
    cudaGetSymbolAddress((void**)&hAt,   hA_tl);
    cudaGetSymbolAddress((void**)&hBt,   hB_tl);
    cudaGetSymbolAddress((void**)&rt,    r_tl);
    cudaGetSymbolAddress((void**)&mstl,  msg_tl);
    cudaGetSymbolAddress((void**)&hallt, hall_tl);

    cudaFuncSetAttribute(gemm_tc1,  cudaFuncAttributeMaxDynamicSharedMemorySize, SMEM_N1);
    cudaFuncSetAttribute(gen_loop,  cudaFuncAttributeMaxDynamicSharedMemorySize, SMEM_P);
    cudaFuncSetAttribute(menc_loop, cudaFuncAttributeMaxDynamicSharedMemorySize, SMEM_P);
    cudaFuncSetAttribute(dec_loop,  cudaFuncAttributeMaxDynamicSharedMemorySize, SMEM_P);

    const dim3 pg(32, 8);                        // persistent grid: 256 CTAs
    const int  cb = (Bsz * Hd) / 256;

    // L0: both gen-phase weight conversions fused
    conv_pair_perm<<<(2 * G4H * Hd + 255) / 256, 256>>>(set_Wih, wstl, gen_Whh, wgtl);
    // L1: attention + all bias preps + m fill fused
    prep_attn<<<Bsz + (4 * G4H + Bsz + 255) / 256, 256>>>(
        input_var, input_mask, embedding, attn_w, attn_b, rt,
        set_bih, set_bhh, pbs, gen_bih, gen_bhh, pbg,
        menc_bih, menc_bhh, pbm, dec_bih, dec_bhh, pbd, m);
    // L2: set encoder cell
    gemm_tc1<<<dim3(32, 4), 256, SMEM_N1>>>(nullptr, G4H, rt, 0, wstl, 16, pbs,
                                            1, c, hA32, hAt);
    // L3: gen persistent loop (ncu target)
    gen_loop<<<pg, 256, SMEM_P>>>(wgtl, pbg, gen_outW, gen_outb, c, mm, m,
                                  hAt, hBt, hA32, hB32, mstl);

    // ---- menc phase ----
    conv_perm_tl<<<(G4H * MVd + 255) / 256, 256>>>(menc_Wih, wmitl, MVd);
    conv_perm_tl<<<(G4H * Hd + 255) / 256, 256>>>(menc_Whh, wmhtl, Hd);
    gemm_tc1<<<dim3(32, (Ld * Bsz) / 128), 256, SMEM_N1>>>(pgm, G4H, mstl, 0,
                                                           wmitl, 1, pbm, 0,
                                                           nullptr, nullptr, nullptr);
    zero_state<<<cb, 256>>>(hA32, c, hAt, Bsz * Hd);
    menc_loop<<<pg, 256, SMEM_P>>>(wmhtl, pgm, c, mm, hAt, hBt, hA32, hB32);
    // Ld = 30 even -> final menc h tiled in hAt

    // ---- dec phase: vocab-factorized input gates ----
    conv_pair_perm<<<(2 * G4H * Hd + 255) / 256, 256>>>(dec_Wih, wditl, dec_Whh, wdhtl);
    conv_tl<<<(Vb * Hd + 255) / 256, 256>>>(embedding, etl, Vb, Hd);
    gemm_tc1<<<dim3(32, Vb / 128), 256, SMEM_N1>>>(ptab, G4H, etl, 0,
                                                   wditl, 16, pbd, 0,
                                                   nullptr, nullptr, nullptr);
    dec_loop<<<pg, 256, SMEM_P>>>(wdhtl, ptab, target_var, c, hAt, hallt);

    // ---- logits (1-product fp16) ----
    conv_tl<<<(Vb * Hd + 255) / 256, 256>>>(dec_outW, wotl, Vb, Hd);
    gemm_tc1<<<dim3(Vb / 128, (Tln * Bsz) / 128), 256, SMEM_N1>>>(
        out, Vb, hallt, 0, wotl, 16, dec_outb, 0, nullptr, nullptr, nullptr);
}

// round 15
// speedup vs baseline: 1.2768x; 1.0078x over previous
#include <cuda_runtime.h>
#include <cuda_fp16.h>
#include <cstdint>

// ---------------- problem constants ----------------
#define Bsz 512
#define Wln 50
#define Tln 50
#define Hd  1024
#define Vb  1024
#define MVd 64
#define Ld  30
#define G4H 4096
#define SOS_INDEX 0
#define EOS_INDEX 1

#define PLANE_B 16384
#define BLKB    32768
#define BLKE    16384
#define GRID_N  256

// ---------------- scratch ----------------
__device__ float d_c   [Bsz * Hd];
__device__ float d_mm  [Ld * Bsz];
__device__ float d_m   [Bsz];
__device__ float d_hA32[Bsz * Hd];
__device__ float d_hB32[Bsz * Hd];
__device__ float pb_set[G4H], pb_gen[G4H], pb_menc[G4H], pb_dec[G4H];
__device__ unsigned g_cnt, g_epoch;
__device__ float pg_menc[Ld * Bsz * G4H];
__device__ float d_ptab [Vb * G4H];

#define TLA __align__(1024)
__device__ TLA __half e_tl   [128 * BLKE];
__device__ TLA __half wset_tl[512 * BLKE];
__device__ TLA __half wgen_tl[512 * BLKE];
__device__ TLA __half wmi_tl [32  * BLKE];
__device__ TLA __half wmh_tl [512 * BLKE];
__device__ TLA __half wdi_tl [512 * BLKE];
__device__ TLA __half wdh_tl [512 * BLKE];
__device__ TLA __half wo_tl  [128 * BLKE];
__device__ TLA __half hA_tl  [64  * BLKE];
__device__ TLA __half hB_tl  [64  * BLKE];
__device__ TLA __half r_tl   [64  * BLKE];
__device__ TLA __half msg_tl [Ld * 4 * BLKE];
__device__ TLA __half hall_tl[Tln * 64 * BLKE];

// ---------------- ptx helpers ----------------
__device__ __forceinline__ uint32_t smem_to_u32(const void* p) {
    uint32_t a;
    asm("{ .reg .u64 t; cvta.to.shared.u64 t, %1; cvt.u32.u64 %0, t; }" : "=r"(a) : "l"(p));
    return a;
}
#define CP_ASYNC16(dst, src) \
    asm volatile("cp.async.cg.shared.global [%0], [%1], 16;" :: "r"(dst), "l"(src))
#define CP_COMMIT() asm volatile("cp.async.commit_group;" ::: "memory")
#define CP_WAIT0()  asm volatile("cp.async.wait_group 0;" ::: "memory")
#define CP_WAIT1()  asm volatile("cp.async.wait_group 1;" ::: "memory")
#define LDSM4(r, a) \
    asm volatile("ldmatrix.sync.aligned.m8n8.x4.shared.b16 {%0,%1,%2,%3}, [%4];" \
        : "=r"((r)[0]), "=r"((r)[1]), "=r"((r)[2]), "=r"((r)[3]) : "r"(a))
#define SWZ(x) ((x) ^ (((x) >> 3) & 0x70))

__device__ __forceinline__ void mma_f16(float* c, const uint32_t* a, const uint32_t* b)
{
    asm volatile(
        "mma.sync.aligned.m16n8k16.row.col.f32.f16.f16.f32 "
        "{%0,%1,%2,%3}, {%4,%5,%6,%7}, {%8,%9}, {%0,%1,%2,%3};\n"
        : "+f"(c[0]), "+f"(c[1]), "+f"(c[2]), "+f"(c[3])
        : "r"(a[0]), "r"(a[1]), "r"(a[2]), "r"(a[3]), "r"(b[0]), "r"(b[1]));
}

__device__ __forceinline__ size_t tlo(int row, int kelem, int KB)
{
    return ((size_t)(row >> 7) * KB + (kelem >> 6)) * BLKB +
           (size_t)SWZ((uint32_t)(((row & 127) << 7) | ((kelem & 63) << 1)));
}

// ---------------- smem layout ----------------
#define SM_TILES  1024
#define NSTAGE    3
#define SGPAD     129
#define STAGE64_B 24576
#define SM_CS     (SM_TILES + NSTAGE * STAGE64_B)   // persistent c slice (8KB)
#define SM_HS     (SM_CS + 8192)                    // persistent h slice (8KB, menc)
#define SMEM_P    (SM_HS + 8192)                    // 91,136 B -> 2 CTAs/SM
#define SMEM_N1   (SM_TILES + NSTAGE * 2 * PLANE_B)

// ---------------- grid barrier ----------------
__device__ __forceinline__ void gbar(unsigned& tgt)
{
    __syncthreads();
    if (threadIdx.x == 0) {
        __threadfence();
        unsigned v = atomicAdd(&g_cnt, 1u);
        if ((v & (GRID_N - 1)) == (GRID_N - 1)) {
            __threadfence();
            atomicAdd(&g_epoch, 1u);
        } else {
            unsigned e;
            do {
                asm volatile("ld.acquire.gpu.global.u32 %0, [%1];"
                             : "=r"(e) : "l"(&g_epoch));
            } while ((int)(e - tgt) < 0);
        }
        __threadfence();
    }
    __syncthreads();
    tgt++;
}

// ---------------- 64x128 1-product GEMM mainloop -----------------------------
__device__ __forceinline__ void gemm_part64(
    float (&acc)[2][4][4], uint32_t sb,
    const char* __restrict__ atl, int ablk,
    const char* __restrict__ wtl, int KB,
    int bm, int bn, int tid)
{
    __syncthreads();
    const uint32_t ahalf = ((uint32_t)(bm >> 6) & 1u) * 8192u;
    auto issue = [&](int kb) {
        const uint32_t stage = sb + SM_TILES + (kb % NSTAGE) * STAGE64_B;
        const char* asrc = atl + ((size_t)(ablk + (bm >> 7) * KB + kb)) * BLKB + ahalf;
        const char* wsrc = wtl + ((size_t)((bn >> 7) * KB + kb)) * BLKB;
        uint32_t ao = (uint32_t)tid * 32;
        CP_ASYNC16(stage + ao,      asrc + ao);
        CP_ASYNC16(stage + ao + 16, asrc + ao + 16);
        uint32_t wo = (uint32_t)tid * 64;
        #pragma unroll
        for (int j = 0; j < 4; j++)
            CP_ASYNC16(stage + 8192 + wo + j * 16, wsrc + wo + j * 16);
        CP_COMMIT();
    };
    issue(0);
    if (KB > 1) issue(1);
    const int wid = tid >> 5, lane = tid & 31;
    const int wm = (wid >> 2) * 32, wn = (wid & 3) * 32;
    for (int kb = 0; kb < KB; kb++) {
        if (kb + 1 < KB) { CP_WAIT1(); } else { CP_WAIT0(); }
        __syncthreads();
        if (kb + 2 < KB) issue(kb + 2);
        const uint32_t stage = sb + SM_TILES + (kb % NSTAGE) * STAGE64_B;
        #pragma unroll
        for (int ks = 0; ks < 4; ks++) {
            uint32_t ah[2][4], bh[4][2];
            {
                const int arow = wm + (lane & 15);
                const int acol = ks * 32 + ((lane >> 4) << 4);
                #pragma unroll
                for (int mt = 0; mt < 2; mt++) {
                    uint32_t off = SWZ((uint32_t)((arow + mt * 16) * 128 + acol));
                    LDSM4(ah[mt], stage + off);
                }
            }
            {
                const int brow = wn + (lane & 7) + ((lane >> 4) << 3);
                const int bcol = ks * 32 + (((lane >> 3) & 1) << 4);
                #pragma unroll
                for (int p2 = 0; p2 < 2; p2++) {
                    uint32_t off = SWZ((uint32_t)((brow + p2 * 16) * 128 + bcol));
                    uint32_t r[4];
                    LDSM4(r, stage + 8192 + off);
                    bh[p2 * 2][0] = r[0]; bh[p2 * 2][1] = r[1];
                    bh[p2 * 2 + 1][0] = r[2]; bh[p2 * 2 + 1][1] = r[3];
                }
            }
            #pragma unroll
            for (int mt = 0; mt < 2; mt++)
                #pragma unroll
                for (int nt = 0; nt < 4; nt++)
                    mma_f16(acc[mt][nt], ah[mt], bh[nt]);
        }
    }
}

// ---------------- 64-row fused LSTM epilogue (smem-resident c/h) -------------
// cs: persistent smem c slice [2048]. hs: persistent smem h slice (mask path) or null.
__device__ __forceinline__ void lstm_epi64(
    float (&acc)[2][4][4], char* smem,
    const float* __restrict__ bias, const float* __restrict__ pg,
    const float* __restrict__ ptab, const int* __restrict__ gidx,
    float* __restrict__ cs, float* __restrict__ hs,
    float* __restrict__ h_f32, char* __restrict__ ht,
    const float* __restrict__ maskp,
    int bm, int bn, int tid)
{
    const int wid = tid >> 5, lane = tid & 31;
    const int wm = (wid >> 2) * 32, wn = (wid & 3) * 32;
    const bool use_pg = (pg != nullptr) || (ptab != nullptr);
    __syncthreads();
    float* sg = (float*)(smem + SM_TILES);
    #pragma unroll
    for (int nt = 0; nt < 4; nt++) {
        const int ln = wn + nt * 8 + 2 * (lane & 3);
        const float bias0 = use_pg ? 0.f : bias[bn + ln];
        const float bias1 = use_pg ? 0.f : bias[bn + ln + 1];
        #pragma unroll
        for (int mt = 0; mt < 2; mt++) {
            const int lm = wm + mt * 16 + (lane >> 2);
            sg[lm * SGPAD + ln]           = acc[mt][nt][0] + bias0;
            sg[lm * SGPAD + ln + 1]       = acc[mt][nt][1] + bias1;
            sg[(lm + 8) * SGPAD + ln]     = acc[mt][nt][2] + bias0;
            sg[(lm + 8) * SGPAD + ln + 1] = acc[mt][nt][3] + bias1;
        }
    }
    __syncthreads();

    const int gu_base = bn >> 2;
    for (int i = tid; i < 64 * 32; i += 256) {
        const int u = i & 31, mrow = i >> 5;
        const float* row = sg + mrow * SGPAD + u * 4;
        float gi_ = row[0], gf_ = row[1], gg_ = row[2], go_ = row[3];
        const int gm = bm + mrow;
        const int ug = gu_base + u;
        if (ptab) {
            int rid = gidx ? gidx[gm] : SOS_INDEX;
            float4 pv = *(const float4*)(ptab + (size_t)rid * G4H + ug * 4);
            gi_ += pv.x; gf_ += pv.y; gg_ += pv.z; go_ += pv.w;
        } else if (pg) {
            float4 pv = *(const float4*)(pg + (size_t)gm * G4H + ug * 4);
            gi_ += pv.x; gf_ += pv.y; gg_ += pv.z; go_ += pv.w;
        }
        float cold = cs[i];
        float si = 1.f / (1.f + expf(-gi_));
        float sf = 1.f / (1.f + expf(-gf_));
        float so = 1.f / (1.f + expf(-go_));
        float cn = sf * cold + si * tanhf(gg_);
        float hn = so * tanhf(cn);
        if (maskp) {
            float mt_ = maskp[gm];
            hn = mt_ * hn + (1.f - mt_) * hs[i];
            cn = mt_ * cn + (1.f - mt_) * cold;
        }
        cs[i] = cn;
        if (hs) hs[i] = hn;
        if (h_f32) h_f32[(size_t)gm * Hd + ug] = hn;
        *(__half*)(ht + tlo(gm, ug, 16)) = __float2half_rn(hn);
    }
}

// ---------------- in-kernel gen output head (2 rows per CTA, 256 CTAs) -------
__device__ __forceinline__ void gen_out_phase(
    char* smem, const float* __restrict__ qf,
    const float* __restrict__ outW, const float* __restrict__ outb,
    char* __restrict__ msg_l, float* __restrict__ mm_l, float* __restrict__ m_state,
    int cta, int tid)
{
    float* hs  = (float*)(smem + SM_TILES);
    float* red = (float*)(smem + SM_TILES + 8192);
    const int slot = tid >> 6, j = tid & 63;
    const int row = cta * 2 + slot;
    if (slot < 2)
        for (int k = j; k < Hd; k += 64)
            hs[slot * Hd + k] = qf[(size_t)row * Hd + k];
    __syncthreads();

    if (slot < 2) {
        float acc = outb[j];
        const float4* h4 = (const float4*)(hs + slot * Hd);
        const float4* w4 = (const float4*)(outW + (size_t)j * Hd);
        #pragma unroll 4
        for (int k = 0; k < Hd / 4; k++) {
            float4 wv = w4[k], hv = h4[k];
            acc += wv.x * hv.x + wv.y * hv.y + wv.z * hv.z + wv.w * hv.w;
        }
        float vmax = acc;
        #pragma unroll
        for (int o = 16; o; o >>= 1) vmax = fmaxf(vmax, __shfl_xor_sync(0xffffffffu, vmax, o));
        if ((j & 31) == 0) red[slot * 2 + (j >> 5)] = vmax;
        __syncwarp();
        __syncthreads();
        vmax = fmaxf(red[slot * 2], red[slot * 2 + 1]);
        float e = expf(acc - vmax);
        float ssum = e;
        #pragma unroll
        for (int o = 16; o; o >>= 1) ssum += __shfl_xor_sync(0xffffffffu, ssum, o);
        __syncthreads();
        if ((j & 31) == 0) red[slot * 2 + (j >> 5)] = ssum;
        __syncthreads();
        ssum = red[slot * 2] + red[slot * 2 + 1];
        float p = e / ssum;
        *(__half*)(msg_l + tlo(row, j, 1)) = __float2half_rn(p);
        if (j == EOS_INDEX) {
            float mo = m_state[row];
            mm_l[row] = mo;
            m_state[row] = mo * (1.f - p);
        }
    } else {
        __syncthreads();
        __syncthreads();
        __syncthreads();
    }
}

#define ZERO_ACC2(acc) { \
    _Pragma("unroll") for (int mt = 0; mt < 2; mt++) \
    _Pragma("unroll") for (int nt = 0; nt < 4; nt++) \
    _Pragma("unroll") for (int i = 0; i < 4; i++) acc[mt][nt][i] = 0.f; }
#define ZERO_ACC4(acc) { \
    _Pragma("unroll") for (int mt = 0; mt < 4; mt++) \
    _Pragma("unroll") for (int nt = 0; nt < 4; nt++) \
    _Pragma("unroll") for (int i = 0; i < 4; i++) acc[mt][nt][i] = 0.f; }

// load per-CTA c slice from gmem into smem
__device__ __forceinline__ void load_cs(float* cs, const float* c, int bm, int bn, int tid)
{
    const int gu_base = bn >> 2;
    for (int i = tid; i < 2048; i += 256)
        cs[i] = c[(size_t)(bm + (i >> 5)) * Hd + gu_base + (i & 31)];
}

// ---------------- persistent loop kernels ------------------------------------
__global__ void __launch_bounds__(256, 2)
gen_loop(const __half* __restrict__ wg, const float* __restrict__ bias,
         const float* __restrict__ outW, const float* __restrict__ outb,
         const float* __restrict__ c0, float* mm, float* m,
         __half* hA, __half* hB, float* fA, float* fB, __half* msg)
{
    extern __shared__ char smem[];
    const uint32_t sb = smem_to_u32(smem);
    const int tid = threadIdx.x;
    const int bm = blockIdx.y * 64, bn = blockIdx.x * 128;
    const int cta = blockIdx.y * 32 + blockIdx.x;
    float* cs = (float*)(smem + SM_CS);
    load_cs(cs, c0, bm, bn, tid);
    unsigned tgt = *((volatile unsigned*)&g_epoch) + 1;
    const char* pt = (const char*)hA;
    char* qt = (char*)hB;
    float* qf = fB;
    float* of = fA;
    float acc[2][4][4];
    for (int l = 0; l < Ld; l++) {
        ZERO_ACC2(acc);
        gemm_part64(acc, sb, pt, 0, (const char*)wg, 16, bm, bn, tid);
        lstm_epi64(acc, smem, bias, nullptr, nullptr, nullptr,
                   cs, nullptr, qf, qt, nullptr, bm, bn, tid);
        gbar(tgt);
        gen_out_phase(smem, qf, outW, outb,
                      (char*)msg + (size_t)l * 4 * BLKB, mm + l * Bsz, m, cta, tid);
        { const char* t = pt; pt = qt; qt = (char*)t; }
        { float* t = qf; qf = of; of = t; }
    }
}

__global__ void __launch_bounds__(256, 2)
menc_loop(const __half* __restrict__ wmh, const float* __restrict__ pgm,
          float* __restrict__ c_out, const float* __restrict__ mm,
          __half* hA, __half* hB)
{
    extern __shared__ char smem[];
    const uint32_t sb = smem_to_u32(smem);
    const int tid = threadIdx.x;
    const int bm = blockIdx.y * 64, bn = blockIdx.x * 128;
    float* cs = (float*)(smem + SM_CS);
    float* hs = (float*)(smem + SM_HS);
    for (int i = tid; i < 2048; i += 256) { cs[i] = 0.f; hs[i] = 0.f; }
    unsigned tgt = *((volatile unsigned*)&g_epoch) + 1;
    const char* pt = (const char*)hA;
    char* qt = (char*)hB;
    float acc[2][4][4];
    for (int l = 0; l < Ld; l++) {
        ZERO_ACC2(acc);
        gbar(tgt);
        gemm_part64(acc, sb, pt, 0, (const char*)wmh, 16, bm, bn, tid);
        lstm_epi64(acc, smem, nullptr, pgm + (size_t)l * Bsz * G4H, nullptr, nullptr,
                   cs, hs, nullptr, qt, mm + l * Bsz, bm, bn, tid);
        { const char* t = pt; pt = qt; qt = (char*)t; }
    }
    // write final c back for the decoder
    const int gu_base = bn >> 2;
    for (int i = tid; i < 2048; i += 256)
        c_out[(size_t)(bm + (i >> 5)) * Hd + gu_base + (i & 31)] = cs[i];
}

__global__ void __launch_bounds__(256, 2)
dec_loop(const __half* __restrict__ wdh, const float* __restrict__ ptab,
         const int* __restrict__ tgt_var,
         const float* __restrict__ c0, const __half* __restrict__ h0t, __half* hallt)
{
    extern __shared__ char smem[];
    const uint32_t sb = smem_to_u32(smem);
    const int tid = threadIdx.x;
    const int bm = blockIdx.y * 64, bn = blockIdx.x * 128;
    float* cs = (float*)(smem + SM_CS);
    load_cs(cs, c0, bm, bn, tid);
    unsigned tgt = *((volatile unsigned*)&g_epoch) + 1;
    float acc[2][4][4];
    for (int t = 0; t < Tln; t++) {
        ZERO_ACC2(acc);
        gbar(tgt);
        const char* a2 = (t == 0) ? (const char*)h0t : (const char*)hallt;
        int ab = (t == 0) ? 0 : (t - 1) * 64;
        gemm_part64(acc, sb, a2, ab, (const char*)wdh, 16, bm, bn, tid);
        const int* gidx = (t == 0) ? nullptr : (tgt_var + (size_t)(t - 1) * Bsz);
        lstm_epi64(acc, smem, nullptr, nullptr, ptab, gidx,
                   cs, nullptr, nullptr,
                   (char*)hallt + (size_t)t * 64 * BLKB, nullptr, bm, bn, tid);
    }
}

// ---------------- standalone GEMM kernel (1-product, 128x128 tiles) ----------
__global__ void __launch_bounds__(256, 2)
gemm_tc1(float* __restrict__ C, int N,
         const __half* __restrict__ a1, int a1base,
         const __half* __restrict__ w1, int KB1,
         const float* __restrict__ bias, int mode,
         float* __restrict__ c_out, float* __restrict__ h_f32,
         __half* __restrict__ ht_out)
{
    extern __shared__ char smem[];
    const uint32_t sb = smem_to_u32(smem);
    const int bm = blockIdx.y * 128, bn = blockIdx.x * 128;
    const int tid = threadIdx.x, wid = tid >> 5, lane = tid & 31;
    const int wm = (wid >> 2) * 64;
    const int wn = (wid & 3) * 32;
    const int nb = KB1;

    auto issue = [&](int kb) {
        const uint32_t stage = sb + SM_TILES + (kb % NSTAGE) * (2 * PLANE_B);
        const char* asrc = (const char*)a1 + ((size_t)(a1base + (bm >> 7) * KB1 + kb)) * BLKB;
        const char* wsrc = (const char*)w1 + ((size_t)((bn >> 7) * KB1 + kb)) * BLKB;
        #pragma unroll
        for (int j = 0; j < 4; j++) {
            uint32_t off = (uint32_t)(tid * 4 + j) * 16;
            CP_ASYNC16(stage + off, asrc + off);
            CP_ASYNC16(stage + PLANE_B + off, wsrc + off);
        }
        CP_COMMIT();
    };

    float acc[4][4][4];
    ZERO_ACC4(acc);

    issue(0);
    if (nb > 1) issue(1);

    for (int kb = 0; kb < nb; kb++) {
        if (kb + 1 < nb) { CP_WAIT1(); } else { CP_WAIT0(); }
        __syncthreads();
        if (kb + 2 < nb) issue(kb + 2);
        const uint32_t stage = sb + SM_TILES + (kb % NSTAGE) * (2 * PLANE_B);

        #pragma unroll
        for (int ks = 0; ks < 4; ks++) {
            uint32_t ah[4][4], bh[4][2];
            {
                const int arow = wm + (lane & 15);
                const int acol = ks * 32 + ((lane >> 4) << 4);
                #pragma unroll
                for (int mt = 0; mt < 4; mt++) {
                    uint32_t off = SWZ((uint32_t)((arow + mt * 16) * 128 + acol));
                    LDSM4(ah[mt], stage + off);
                }
            }
            {
                const int brow = wn + (lane & 7) + ((lane >> 4) << 3);
                const int bcol = ks * 32 + (((lane >> 3) & 1) << 4);
                #pragma unroll
                for (int p2 = 0; p2 < 2; p2++) {
                    uint32_t off = SWZ((uint32_t)((brow + p2 * 16) * 128 + bcol));
                    uint32_t r[4];
                    LDSM4(r, stage + PLANE_B + off);
                    bh[p2 * 2][0] = r[0]; bh[p2 * 2][1] = r[1];
                    bh[p2 * 2 + 1][0] = r[2]; bh[p2 * 2 + 1][1] = r[3];
                }
            }
            #pragma unroll
            for (int mt = 0; mt < 4; mt++)
                #pragma unroll
                for (int nt = 0; nt < 4; nt++)
                    mma_f16(acc[mt][nt], ah[mt], bh[nt]);
        }
    }

    if (mode == 0) {
        #pragma unroll
        for (int nt = 0; nt < 4; nt++) {
            const int n0 = bn + wn + nt * 8 + 2 * (lane & 3);
            float bias0 = bias ? bias[n0] : 0.f;
            float bias1 = bias ? bias[n0 + 1] : 0.f;
            #pragma unroll
            for (int mt = 0; mt < 4; mt++) {
                const int m0 = bm + wm + mt * 16 + (lane >> 2);
                float2 v0 = make_float2(acc[mt][nt][0] + bias0, acc[mt][nt][1] + bias1);
                float2 v1 = make_float2(acc[mt][nt][2] + bias0, acc[mt][nt][3] + bias1);
                *(float2*)&C[(size_t)m0 * N + n0] = v0;
                *(float2*)&C[(size_t)(m0 + 8) * N + n0] = v1;
            }
        }
        return;
    }

    // 128-row fused LSTM epilogue (set encoder; c_in == 0)
    __syncthreads();
    float* sg = (float*)(smem + SM_TILES);
    #pragma unroll
    for (int nt = 0; nt < 4; nt++) {
        const int ln = wn + nt * 8 + 2 * (lane & 3);
        const float bias0 = bias[bn + ln];
        const float bias1 = bias[bn + ln + 1];
        #pragma unroll
        for (int mt = 0; mt < 4; mt++) {
            const int lm = wm + mt * 16 + (lane >> 2);
            sg[lm * SGPAD + ln]           = acc[mt][nt][0] + bias0;
            sg[lm * SGPAD + ln + 1]       = acc[mt][nt][1] + bias1;
            sg[(lm + 8) * SGPAD + ln]     = acc[mt][nt][2] + bias0;
            sg[(lm + 8) * SGPAD + ln + 1] = acc[mt][nt][3] + bias1;
        }
    }
    __syncthreads();
    const int gu_base = bn >> 2;
    char* ht = (char*)ht_out;
    for (int i = tid; i < 128 * 32; i += 256) {
        const int u = i & 31, mrow = i >> 5;
        const float* row = sg + mrow * SGPAD + u * 4;
        float gi_ = row[0], gg_ = row[2], go_ = row[3];
        const int gm = bm + mrow;
        const int ug = gu_base + u;
        const size_t ci = (size_t)gm * Hd + ug;
        float si = 1.f / (1.f + expf(-gi_));
        float so = 1.f / (1.f + expf(-go_));
        float cn = si * tanhf(gg_);
        float hn = so * tanhf(cn);
        c_out[ci] = cn;
        if (h_f32) h_f32[ci] = hn;
        *(__half*)(ht + tlo(gm, ug, 16)) = __float2half_rn(hn);
    }
}

// ---------------- conversion / pre-tiling kernels (hi plane only) -----------
__device__ __forceinline__ void conv_perm_one(const float* s, __half* dst, int K, int i)
{
    int np = i / K, k = i - np * K;
    int u = np >> 2, g = np & 3;
    float x = s[(size_t)(g * Hd + u) * K + k];
    *(__half*)((char*)dst + tlo(np, k, K >> 6)) = __float2half_rn(x);
}

__global__ void conv_perm_tl(const float* __restrict__ s, __half* __restrict__ dst, int K)
{
    int i = blockIdx.x * blockDim.x + threadIdx.x;
    if (i >= G4H * K) return;
    conv_perm_one(s, dst, K, i);
}

__global__ void conv_pair_perm(const float* __restrict__ s0, __half* __restrict__ d0,
                               const float* __restrict__ s1, __half* __restrict__ d1)
{
    int i = blockIdx.x * blockDim.x + threadIdx.x;
    if (i < G4H * Hd) conv_perm_one(s0, d0, Hd, i);
    else if (i < 2 * G4H * Hd) conv_perm_one(s1, d1, Hd, i - G4H * Hd);
}

__global__ void conv_tl(const float* __restrict__ s, __half* __restrict__ dst,
                        int rows, int K)
{
    int i = blockIdx.x * blockDim.x + threadIdx.x;
    if (i >= rows * K) return;
    int np = i / K, k = i - np * K;
    *(__half*)((char*)dst + tlo(np, k, K >> 6)) = __float2half_rn(s[(size_t)np * K + k]);
}

// fused: attention (blocks 0..511) + bias prep / m fill (blocks 512+)
__global__ void prep_attn(const int* __restrict__ inp, const float* __restrict__ mask,
                          const float* __restrict__ emb, const float* __restrict__ attn_w,
                          const float* __restrict__ attn_b, __half* __restrict__ rtl,
                          const float* sb1, const float* sb2, float* so,
                          const float* gb1, const float* gb2, float* go,
                          const float* mb1, const float* mb2, float* mo,
                          const float* db1, const float* db2, float* dopt,
                          float* m)
{
    __shared__ float aw[Wln];
    __shared__ int   idxs[Wln];
    const int tid = threadIdx.x;

    if (blockIdx.x >= Bsz) {
        int i = (blockIdx.x - Bsz) * 256 + tid;
        if (i < 4 * G4H) {
            int set = i >> 12, np = i & (G4H - 1);
            int u = np >> 2, g = np & 3;
            int src = g * Hd + u;
            float v; float* o;
            if (set == 0)      { v = sb1[src] + sb2[src]; o = so; }
            else if (set == 1) { v = gb1[src] + gb2[src]; o = go; }
            else if (set == 2) { v = mb1[src] + mb2[src]; o = mo; }
            else               { v = db1[src] + db2[src]; o = dopt; }
            o[np] = v;
        } else if (i < 4 * G4H + Bsz) {
            m[i - 4 * G4H] = 1.f;
        }
        return;
    }

    const int b = blockIdx.x;
    const int lane = tid & 31, wrp = tid >> 5;
    if (tid < Wln) idxs[tid] = inp[b * Wln + tid];
    __syncthreads();
    const float* w2 = attn_w + Hd;
    for (int wi = wrp; wi < Wln; wi += 8) {
        const float* e = emb + (size_t)idxs[wi] * Hd;
        float acc = 0.f;
        for (int k = lane; k < Hd; k += 32) acc += e[k] * w2[k];
        #pragma unroll
        for (int o = 16; o; o >>= 1) acc += __shfl_xor_sync(0xffffffffu, acc, o);
        if (lane == 0) {
            float a = 1.f / (1.f + expf(-(acc + attn_b[0])));
            aw[wi] = a * mask[wi * Bsz + b];
        }
    }
    __syncthreads();
    char* d = (char*)rtl;
    for (int hh = tid; hh < Hd; hh += 256) {
        float acc = 0.f;
        #pragma unroll 5
        for (int wi = 0; wi < Wln; wi++)
            acc += aw[wi] * emb[(size_t)idxs[wi] * Hd + hh];
        *(__half*)(d + tlo(b, hh, 16)) = __float2half_rn(acc);
    }
}

// zero the FULL tiled h buffer (2n halfs: hi + lo plane bytes)
__global__ void zero_htl(__half* htl, int n2)
{
    int i = blockIdx.x * blockDim.x + threadIdx.x;
    if (i < n2) htl[i] = __float2half_rn(0.f);
}

// ---------------- host orchestration ----------------
extern "C" void kernel_launch(void* const* d_in, const int* in_sizes, int n_in,
                              void* d_out, int out_size)
{
    const int s = (in_sizes[3] == 1) ? 1 : 0;

    const int*   input_var  = (const int*)  d_in[0];
    const float* input_mask = (const float*)d_in[1];
    const int*   target_var = (const int*)  d_in[2];
    const float* embedding  = (const float*)d_in[3 + s];
    const float* attn_w     = (const float*)d_in[4 + s];
    const float* attn_b     = (const float*)d_in[5 + s];
    const float* set_Wih    = (const float*)d_in[6 + s];
    const float* set_bih    = (const float*)d_in[8 + s];
    const float* set_bhh    = (const float*)d_in[9 + s];
    const float* gen_Whh    = (const float*)d_in[14 + s];
    const float* gen_bih    = (const float*)d_in[15 + s];
    const float* gen_bhh    = (const float*)d_in[16 + s];
    const float* gen_outW   = (const float*)d_in[17 + s];
    const float* gen_outb   = (const float*)d_in[18 + s];
    const float* menc_Wih   = (const float*)d_in[19 + s];
    const float* menc_Whh   = (const float*)d_in[20 + s];
    const float* menc_bih   = (const float*)d_in[21 + s];
    const float* menc_bhh   = (const float*)d_in[22 + s];
    const float* dec_Wih    = (const float*)d_in[25 + s];
    const float* dec_Whh    = (const float*)d_in[26 + s];
    const float* dec_bih    = (const float*)d_in[27 + s];
    const float* dec_bhh    = (const float*)d_in[28 + s];
    const float* dec_outW   = (const float*)d_in[29 + s];
    const float* dec_outb   = (const float*)d_in[30 + s];
    float* out = (float*)d_out;

    float *c, *mm, *m, *hA32, *hB32, *pbs, *pbg, *pbm, *pbd, *pgm, *ptab;
    cudaGetSymbolAddress((void**)&c,    d_c);
    cudaGetSymbolAddress((void**)&mm,   d_mm);
    cudaGetSymbolAddress((void**)&m,    d_m);
    cudaGetSymbolAddress((void**)&hA32, d_hA32);
    cudaGetSymbolAddress((void**)&hB32, d_hB32);
    cudaGetSymbolAddress((void**)&pbs, pb_set);  cudaGetSymbolAddress((void**)&pbg, pb_gen);
    cudaGetSymbolAddress((void**)&pbm, pb_menc); cudaGetSymbolAddress((void**)&pbd, pb_dec);
    cudaGetSymbolAddress((void**)&pgm, pg_menc); cudaGetSymbolAddress((void**)&ptab, d_ptab);
    __half *etl, *wstl, *wgtl, *wmitl, *wmhtl, *wditl, *wdhtl, *wotl;
    __half *hAt, *hBt, *rt, *mstl, *hallt;
    cudaGetSymbolAddress((void**)&etl,   e_tl);
    cudaGetSymbolAddress((void**)&wstl,  wset_tl);
    cudaGetSymbolAddress((void**)&wgtl,  wgen_tl);
    cudaGetSymbolAddress((void**)&wmitl, wmi_tl);
    cudaGetSymbolAddress((void**)&wmhtl, wmh_tl);
    cudaGetSymbolAddress((void**)&wditl, wdi_tl);
    cudaGetSymbolAddress((void**)&wdhtl, wdh_tl);
    cudaGetSymbolAddress((void**)&wotl,  wo_tl);
    cudaGetSymbolAddress((void**)&hAt,   hA_tl);
    cudaGetSymbolAddress((void**)&hBt,   hB_tl);
    cudaGetSymbolAddress((void**)&rt,    r_tl);
    cudaGetSymbolAddress((void**)&mstl,  msg_tl);
    cudaGetSymbolAddress((void**)&hallt, hall_tl);

    cudaFuncSetAttribute(gemm_tc1,  cudaFuncAttributeMaxDynamicSharedMemorySize, SMEM_N1);
    cudaFuncSetAttribute(gen_loop,  cudaFuncAttributeMaxDynamicSharedMemorySize, SMEM_P);
    cudaFuncSetAttribute(menc_loop, cudaFuncAttributeMaxDynamicSharedMemorySize, SMEM_P);
    cudaFuncSetAttribute(dec_loop,  cudaFuncAttributeMaxDynamicSharedMemorySize, SMEM_P);

    const dim3 pg(32, 8);                        // persistent grid: 256 CTAs

    // L0: both gen-phase weight conversions fused
    conv_pair_perm<<<(2 * G4H * Hd + 255) / 256, 256>>>(set_Wih, wstl, gen_Whh, wgtl);
    // L1: attention + all bias preps + m fill fused
    prep_attn<<<Bsz + (4 * G4H + Bsz + 255) / 256, 256>>>(
        input_var, input_mask, embedding, attn_w, attn_b, rt,
        set_bih, set_bhh, pbs, gen_bih, gen_bhh, pbg,
        menc_bih, menc_bhh, pbm, dec_bih, dec_bhh, pbd, m);
    // L2: set encoder cell -> c (gmem) + hAt tiled
    gemm_tc1<<<dim3(32, 4), 256, SMEM_N1>>>(nullptr, G4H, rt, 0, wstl, 16, pbs,
                                            1, c, nullptr, hAt);
    // L3: gen persistent loop (c resident in smem)
    gen_loop<<<pg, 256, SMEM_P>>>(wgtl, pbg, gen_outW, gen_outb, c, mm, m,
                                  hAt, hBt, hA32, hB32, mstl);

    // ---- menc phase ----
    conv_perm_tl<<<(G4H * MVd + 255) / 256, 256>>>(menc_Wih, wmitl, MVd);
    conv_perm_tl<<<(G4H * Hd + 255) / 256, 256>>>(menc_Whh, wmhtl, Hd);
    gemm_tc1<<<dim3(32, (Ld * Bsz) / 128), 256, SMEM_N1>>>(pgm, G4H, mstl, 0,
                                                           wmitl, 1, pbm, 0,
                                                           nullptr, nullptr, nullptr);
    zero_htl<<<(2 * Bsz * Hd + 255) / 256, 256>>>(hAt, 2 * Bsz * Hd);   // FULL buffer
    menc_loop<<<pg, 256, SMEM_P>>>(wmhtl, pgm, c, mm, hAt, hBt);
    // Ld = 30 even -> final menc h tiled in hAt; c written back to gmem

    // ---- dec phase: vocab-factorized input gates ----
    conv_pair_perm<<<(2 * G4H * Hd + 255) / 256, 256>>>(dec_Wih, wditl, dec_Whh, wdhtl);
    conv_tl<<<(Vb * Hd + 255) / 256, 256>>>(embedding, etl, Vb, Hd);
    gemm_tc1<<<dim3(32, Vb / 128), 256, SMEM_N1>>>(ptab, G4H, etl, 0,
                                                   wditl, 16, pbd, 0,
                                                   nullptr, nullptr, nullptr);
    dec_loop<<<pg, 256, SMEM_P>>>(wdhtl, ptab, target_var, c, hAt, hallt);

    // ---- logits (1-product fp16) ----
    conv_tl<<<(Vb * Hd + 255) / 256, 256>>>(dec_outW, wotl, Vb, Hd);
    gemm_tc1<<<dim3(Vb / 128, (Tln * Bsz) / 128), 256, SMEM_N1>>>(
        out, Vb, hallt, 0, wotl, 16, dec_outb, 0, nullptr, nullptr, nullptr);
}

// round 16
// speedup vs baseline: 1.3313x; 1.0426x over previous
#include <cuda_runtime.h>
#include <cuda_fp16.h>
#include <cstdint>

// ---------------- problem constants ----------------
#define Bsz 512
#define Wln 50
#define Tln 50
#define Hd  1024
#define Vb  1024
#define MVd 64
#define Ld  30
#define G4H 4096
#define SOS_INDEX 0
#define EOS_INDEX 1

#define PLANE_B 16384
#define BLKB    32768
#define BLKE    16384
#define GRPN    32             // CTAs per barrier group (one row-group)

// ---------------- scratch ----------------
__device__ float d_c   [Bsz * Hd];
__device__ float d_mm  [Ld * Bsz];
__device__ float d_m   [Bsz];
__device__ float d_hA32[Bsz * Hd];
__device__ float d_hB32[Bsz * Hd];
__device__ float pb_set[G4H], pb_gen[G4H], pb_menc[G4H], pb_dec[G4H];
__device__ unsigned g_cnt[8], g_epoch[8];
__device__ float pg_menc[Ld * Bsz * G4H];
__device__ float d_ptab [Vb * G4H];

#define TLA __align__(1024)
__device__ TLA __half e_tl   [128 * BLKE];
__device__ TLA __half wset_tl[512 * BLKE];
__device__ TLA __half wgen_tl[512 * BLKE];
__device__ TLA __half wmi_tl [32  * BLKE];
__device__ TLA __half wmh_tl [512 * BLKE];
__device__ TLA __half wdi_tl [512 * BLKE];
__device__ TLA __half wdh_tl [512 * BLKE];
__device__ TLA __half wo_tl  [128 * BLKE];
__device__ TLA __half hA_tl  [64  * BLKE];
__device__ TLA __half hB_tl  [64  * BLKE];
__device__ TLA __half r_tl   [64  * BLKE];
__device__ TLA __half msg_tl [Ld * 4 * BLKE];
__device__ TLA __half hall_tl[Tln * 64 * BLKE];

// ---------------- ptx helpers ----------------
__device__ __forceinline__ uint32_t smem_to_u32(const void* p) {
    uint32_t a;
    asm("{ .reg .u64 t; cvta.to.shared.u64 t, %1; cvt.u32.u64 %0, t; }" : "=r"(a) : "l"(p));
    return a;
}
#define CP_ASYNC16(dst, src) \
    asm volatile("cp.async.cg.shared.global [%0], [%1], 16;" :: "r"(dst), "l"(src))
#define CP_COMMIT() asm volatile("cp.async.commit_group;" ::: "memory")
#define CP_WAIT0()  asm volatile("cp.async.wait_group 0;" ::: "memory")
#define CP_WAIT1()  asm volatile("cp.async.wait_group 1;" ::: "memory")
#define LDSM4(r, a) \
    asm volatile("ldmatrix.sync.aligned.m8n8.x4.shared.b16 {%0,%1,%2,%3}, [%4];" \
        : "=r"((r)[0]), "=r"((r)[1]), "=r"((r)[2]), "=r"((r)[3]) : "r"(a))
#define SWZ(x) ((x) ^ (((x) >> 3) & 0x70))

__device__ __forceinline__ void mma_f16(float* c, const uint32_t* a, const uint32_t* b)
{
    asm volatile(
        "mma.sync.aligned.m16n8k16.row.col.f32.f16.f16.f32 "
        "{%0,%1,%2,%3}, {%4,%5,%6,%7}, {%8,%9}, {%0,%1,%2,%3};\n"
        : "+f"(c[0]), "+f"(c[1]), "+f"(c[2]), "+f"(c[3])
        : "r"(a[0]), "r"(a[1]), "r"(a[2]), "r"(a[3]), "r"(b[0]), "r"(b[1]));
}

__device__ __forceinline__ size_t tlo(int row, int kelem, int KB)
{
    return ((size_t)(row >> 7) * KB + (kelem >> 6)) * BLKB +
           (size_t)SWZ((uint32_t)(((row & 127) << 7) | ((kelem & 63) << 1)));
}

// ---------------- smem layout ----------------
#define SM_TILES  1024
#define NSTAGE    3
#define SGPAD     129
#define STAGE64_B 24576
#define SM_CS     (SM_TILES + NSTAGE * STAGE64_B)
#define SM_HS     (SM_CS + 8192)
#define SMEM_P    (SM_HS + 8192)                    // 91,136 B -> 2 CTAs/SM
#define SMEM_N1   (SM_TILES + NSTAGE * 2 * PLANE_B)

// ---------------- per-group grid barrier (32 CTAs, monotonic) ----------------
__device__ __forceinline__ void gbar(unsigned& tgt, int grp)
{
    __syncthreads();
    if (threadIdx.x == 0) {
        __threadfence();
        unsigned v = atomicAdd(&g_cnt[grp], 1u);
        if ((v & (GRPN - 1)) == (GRPN - 1)) {
            __threadfence();
            atomicAdd(&g_epoch[grp], 1u);
        } else {
            unsigned e;
            do {
                asm volatile("ld.acquire.gpu.global.u32 %0, [%1];"
                             : "=r"(e) : "l"(&g_epoch[grp]));
            } while ((int)(e - tgt) < 0);
        }
        __threadfence();
    }
    __syncthreads();
    tgt++;
}

// ---------------- 64x128 1-product GEMM mainloop -----------------------------
__device__ __forceinline__ void gemm_part64(
    float (&acc)[2][4][4], uint32_t sb,
    const char* __restrict__ atl, int ablk,
    const char* __restrict__ wtl, int KB,
    int bm, int bn, int tid)
{
    __syncthreads();
    const uint32_t ahalf = ((uint32_t)(bm >> 6) & 1u) * 8192u;
    auto issue = [&](int kb) {
        const uint32_t stage = sb + SM_TILES + (kb % NSTAGE) * STAGE64_B;
        const char* asrc = atl + ((size_t)(ablk + (bm >> 7) * KB + kb)) * BLKB + ahalf;
        const char* wsrc = wtl + ((size_t)((bn >> 7) * KB + kb)) * BLKB;
        uint32_t ao = (uint32_t)tid * 32;
        CP_ASYNC16(stage + ao,      asrc + ao);
        CP_ASYNC16(stage + ao + 16, asrc + ao + 16);
        uint32_t wo = (uint32_t)tid * 64;
        #pragma unroll
        for (int j = 0; j < 4; j++)
            CP_ASYNC16(stage + 8192 + wo + j * 16, wsrc + wo + j * 16);
        CP_COMMIT();
    };
    issue(0);
    if (KB > 1) issue(1);
    const int wid = tid >> 5, lane = tid & 31;
    const int wm = (wid >> 2) * 32, wn = (wid & 3) * 32;
    for (int kb = 0; kb < KB; kb++) {
        if (kb + 1 < KB) { CP_WAIT1(); } else { CP_WAIT0(); }
        __syncthreads();
        if (kb + 2 < KB) issue(kb + 2);
        const uint32_t stage = sb + SM_TILES + (kb % NSTAGE) * STAGE64_B;
        #pragma unroll
        for (int ks = 0; ks < 4; ks++) {
            uint32_t ah[2][4], bh[4][2];
            {
                const int arow = wm + (lane & 15);
                const int acol = ks * 32 + ((lane >> 4) << 4);
                #pragma unroll
                for (int mt = 0; mt < 2; mt++) {
                    uint32_t off = SWZ((uint32_t)((arow + mt * 16) * 128 + acol));
                    LDSM4(ah[mt], stage + off);
                }
            }
            {
                const int brow = wn + (lane & 7) + ((lane >> 4) << 3);
                const int bcol = ks * 32 + (((lane >> 3) & 1) << 4);
                #pragma unroll
                for (int p2 = 0; p2 < 2; p2++) {
                    uint32_t off = SWZ((uint32_t)((brow + p2 * 16) * 128 + bcol));
                    uint32_t r[4];
                    LDSM4(r, stage + 8192 + off);
                    bh[p2 * 2][0] = r[0]; bh[p2 * 2][1] = r[1];
                    bh[p2 * 2 + 1][0] = r[2]; bh[p2 * 2 + 1][1] = r[3];
                }
            }
            #pragma unroll
            for (int mt = 0; mt < 2; mt++)
                #pragma unroll
                for (int nt = 0; nt < 4; nt++)
                    mma_f16(acc[mt][nt], ah[mt], bh[nt]);
        }
    }
}

// ---------------- 64-row fused LSTM epilogue (smem-resident c/h) -------------
__device__ __forceinline__ void lstm_epi64(
    float (&acc)[2][4][4], char* smem,
    const float* __restrict__ bias, const float* __restrict__ pg,
    const float* __restrict__ ptab, const int* __restrict__ gidx,
    float* __restrict__ cs, float* __restrict__ hs,
    float* __restrict__ h_f32, char* __restrict__ ht,
    const float* __restrict__ maskp,
    int bm, int bn, int tid)
{
    const int wid = tid >> 5, lane = tid & 31;
    const int wm = (wid >> 2) * 32, wn = (wid & 3) * 32;
    const bool use_pg = (pg != nullptr) || (ptab != nullptr);
    __syncthreads();
    float* sg = (float*)(smem + SM_TILES);
    #pragma unroll
    for (int nt = 0; nt < 4; nt++) {
        const int ln = wn + nt * 8 + 2 * (lane & 3);
        const float bias0 = use_pg ? 0.f : bias[bn + ln];
        const float bias1 = use_pg ? 0.f : bias[bn + ln + 1];
        #pragma unroll
        for (int mt = 0; mt < 2; mt++) {
            const int lm = wm + mt * 16 + (lane >> 2);
            sg[lm * SGPAD + ln]           = acc[mt][nt][0] + bias0;
            sg[lm * SGPAD + ln + 1]       = acc[mt][nt][1] + bias1;
            sg[(lm + 8) * SGPAD + ln]     = acc[mt][nt][2] + bias0;
            sg[(lm + 8) * SGPAD + ln + 1] = acc[mt][nt][3] + bias1;
        }
    }
    __syncthreads();

    const int gu_base = bn >> 2;
    for (int i = tid; i < 64 * 32; i += 256) {
        const int u = i & 31, mrow = i >> 5;
        const float* row = sg + mrow * SGPAD + u * 4;
        float gi_ = row[0], gf_ = row[1], gg_ = row[2], go_ = row[3];
        const int gm = bm + mrow;
        const int ug = gu_base + u;
        if (ptab) {
            int rid = gidx ? gidx[gm] : SOS_INDEX;
            float4 pv = *(const float4*)(ptab + (size_t)rid * G4H + ug * 4);
            gi_ += pv.x; gf_ += pv.y; gg_ += pv.z; go_ += pv.w;
        } else if (pg) {
            float4 pv = *(const float4*)(pg + (size_t)gm * G4H + ug * 4);
            gi_ += pv.x; gf_ += pv.y; gg_ += pv.z; go_ += pv.w;
        }
        float cold = cs[i];
        float si = 1.f / (1.f + expf(-gi_));
        float sf = 1.f / (1.f + expf(-gf_));
        float so = 1.f / (1.f + expf(-go_));
        float cn = sf * cold + si * tanhf(gg_);
        float hn = so * tanhf(cn);
        if (maskp) {
            float mt_ = maskp[gm];
            hn = mt_ * hn + (1.f - mt_) * hs[i];
            cn = mt_ * cn + (1.f - mt_) * cold;
        }
        cs[i] = cn;
        if (hs) hs[i] = hn;
        if (h_f32) h_f32[(size_t)gm * Hd + ug] = hn;
        *(__half*)(ht + tlo(gm, ug, 16)) = __float2half_rn(hn);
    }
}

// ---------------- in-kernel gen output head (2 rows per CTA, 256 CTAs) -------
__device__ __forceinline__ void gen_out_phase(
    char* smem, const float* __restrict__ qf,
    const float* __restrict__ outW, const float* __restrict__ outb,
    char* __restrict__ msg_l, float* __restrict__ mm_l, float* __restrict__ m_state,
    int cta, int tid)
{
    float* hs  = (float*)(smem + SM_TILES);
    float* red = (float*)(smem + SM_TILES + 8192);
    const int slot = tid >> 6, j = tid & 63;
    const int row = cta * 2 + slot;
    if (slot < 2)
        for (int k = j; k < Hd; k += 64)
            hs[slot * Hd + k] = qf[(size_t)row * Hd + k];
    __syncthreads();

    if (slot < 2) {
        float acc = outb[j];
        const float4* h4 = (const float4*)(hs + slot * Hd);
        const float4* w4 = (const float4*)(outW + (size_t)j * Hd);
        #pragma unroll 4
        for (int k = 0; k < Hd / 4; k++) {
            float4 wv = w4[k], hv = h4[k];
            acc += wv.x * hv.x + wv.y * hv.y + wv.z * hv.z + wv.w * hv.w;
        }
        float vmax = acc;
        #pragma unroll
        for (int o = 16; o; o >>= 1) vmax = fmaxf(vmax, __shfl_xor_sync(0xffffffffu, vmax, o));
        if ((j & 31) == 0) red[slot * 2 + (j >> 5)] = vmax;
        __syncwarp();
        __syncthreads();
        vmax = fmaxf(red[slot * 2], red[slot * 2 + 1]);
        float e = expf(acc - vmax);
        float ssum = e;
        #pragma unroll
        for (int o = 16; o; o >>= 1) ssum += __shfl_xor_sync(0xffffffffu, ssum, o);
        __syncthreads();
        if ((j & 31) == 0) red[slot * 2 + (j >> 5)] = ssum;
        __syncthreads();
        ssum = red[slot * 2] + red[slot * 2 + 1];
        float p = e / ssum;
        *(__half*)(msg_l + tlo(row, j, 1)) = __float2half_rn(p);
        if (j == EOS_INDEX) {
            float mo = m_state[row];
            mm_l[row] = mo;
            m_state[row] = mo * (1.f - p);
        }
    } else {
        __syncthreads();
        __syncthreads();
        __syncthreads();
    }
}

#define ZERO_ACC2(acc) { \
    _Pragma("unroll") for (int mt = 0; mt < 2; mt++) \
    _Pragma("unroll") for (int nt = 0; nt < 4; nt++) \
    _Pragma("unroll") for (int i = 0; i < 4; i++) acc[mt][nt][i] = 0.f; }
#define ZERO_ACC4(acc) { \
    _Pragma("unroll") for (int mt = 0; mt < 4; mt++) \
    _Pragma("unroll") for (int nt = 0; nt < 4; nt++) \
    _Pragma("unroll") for (int i = 0; i < 4; i++) acc[mt][nt][i] = 0.f; }

__device__ __forceinline__ void load_cs(float* cs, const float* c, int bm, int bn, int tid)
{
    const int gu_base = bn >> 2;
    for (int i = tid; i < 2048; i += 256)
        cs[i] = c[(size_t)(bm + (i >> 5)) * Hd + gu_base + (i & 31)];
}

// ---------------- persistent loop kernels (group barriers) -------------------
__global__ void __launch_bounds__(256, 2)
gen_loop(const __half* __restrict__ wg, const float* __restrict__ bias,
         const float* __restrict__ outW, const float* __restrict__ outb,
         const float* __restrict__ c0, float* mm, float* m,
         __half* hA, __half* hB, float* fA, float* fB, __half* msg)
{
    extern __shared__ char smem[];
    const uint32_t sb = smem_to_u32(smem);
    const int tid = threadIdx.x;
    const int bm = blockIdx.y * 64, bn = blockIdx.x * 128;
    const int cta = blockIdx.y * 32 + blockIdx.x;
    const int grp = blockIdx.y;
    float* cs = (float*)(smem + SM_CS);
    load_cs(cs, c0, bm, bn, tid);
    unsigned tgt = *((volatile unsigned*)&g_epoch[grp]) + 1;
    const char* pt = (const char*)hA;
    char* qt = (char*)hB;
    float* qf = fB;
    float* of = fA;
    float acc[2][4][4];
    for (int l = 0; l < Ld; l++) {
        ZERO_ACC2(acc);
        gemm_part64(acc, sb, pt, 0, (const char*)wg, 16, bm, bn, tid);
        lstm_epi64(acc, smem, bias, nullptr, nullptr, nullptr,
                   cs, nullptr, qf, qt, nullptr, bm, bn, tid);
        gbar(tgt, grp);
        gen_out_phase(smem, qf, outW, outb,
                      (char*)msg + (size_t)l * 4 * BLKB, mm + l * Bsz, m, cta, tid);
        { const char* t = pt; pt = qt; qt = (char*)t; }
        { float* t = qf; qf = of; of = t; }
    }
}

__global__ void __launch_bounds__(256, 2)
menc_loop(const __half* __restrict__ wmh, const float* __restrict__ pgm,
          float* __restrict__ c_out, const float* __restrict__ mm,
          __half* hA, __half* hB)
{
    extern __shared__ char smem[];
    const uint32_t sb = smem_to_u32(smem);
    const int tid = threadIdx.x;
    const int bm = blockIdx.y * 64, bn = blockIdx.x * 128;
    const int grp = blockIdx.y;
    float* cs = (float*)(smem + SM_CS);
    float* hs = (float*)(smem + SM_HS);
    for (int i = tid; i < 2048; i += 256) { cs[i] = 0.f; hs[i] = 0.f; }
    unsigned tgt = *((volatile unsigned*)&g_epoch[grp]) + 1;
    const char* pt = (const char*)hA;
    char* qt = (char*)hB;
    float acc[2][4][4];
    for (int l = 0; l < Ld; l++) {
        ZERO_ACC2(acc);
        gbar(tgt, grp);
        gemm_part64(acc, sb, pt, 0, (const char*)wmh, 16, bm, bn, tid);
        lstm_epi64(acc, smem, nullptr, pgm + (size_t)l * Bsz * G4H, nullptr, nullptr,
                   cs, hs, nullptr, qt, mm + l * Bsz, bm, bn, tid);
        { const char* t = pt; pt = qt; qt = (char*)t; }
    }
    const int gu_base = bn >> 2;
    for (int i = tid; i < 2048; i += 256)
        c_out[(size_t)(bm + (i >> 5)) * Hd + gu_base + (i & 31)] = cs[i];
}

__global__ void __launch_bounds__(256, 2)
dec_loop(const __half* __restrict__ wdh, const float* __restrict__ ptab,
         const int* __restrict__ tgt_var,
         const float* __restrict__ c0, const __half* __restrict__ h0t, __half* hallt)
{
    extern __shared__ char smem[];
    const uint32_t sb = smem_to_u32(smem);
    const int tid = threadIdx.x;
    const int bm = blockIdx.y * 64, bn = blockIdx.x * 128;
    const int grp = blockIdx.y;
    float* cs = (float*)(smem + SM_CS);
    load_cs(cs, c0, bm, bn, tid);
    unsigned tgt = *((volatile unsigned*)&g_epoch[grp]) + 1;
    float acc[2][4][4];
    for (int t = 0; t < Tln; t++) {
        ZERO_ACC2(acc);
        gbar(tgt, grp);
        const char* a2 = (t == 0) ? (const char*)h0t : (const char*)hallt;
        int ab = (t == 0) ? 0 : (t - 1) * 64;
        gemm_part64(acc, sb, a2, ab, (const char*)wdh, 16, bm, bn, tid);
        const int* gidx = (t == 0) ? nullptr : (tgt_var + (size_t)(t - 1) * Bsz);
        lstm_epi64(acc, smem, nullptr, nullptr, ptab, gidx,
                   cs, nullptr, nullptr,
                   (char*)hallt + (size_t)t * 64 * BLKB, nullptr, bm, bn, tid);
    }
}

// ---------------- standalone GEMM kernel (1-product, 128x128 tiles) ----------
__global__ void __launch_bounds__(256, 2)
gemm_tc1(float* __restrict__ C, int N,
         const __half* __restrict__ a1, int a1base,
         const __half* __restrict__ w1, int KB1,
         const float* __restrict__ bias, int mode,
         float* __restrict__ c_out, float* __restrict__ h_f32,
         __half* __restrict__ ht_out)
{
    extern __shared__ char smem[];
    const uint32_t sb = smem_to_u32(smem);
    const int bm = blockIdx.y * 128, bn = blockIdx.x * 128;
    const int tid = threadIdx.x, wid = tid >> 5, lane = tid & 31;
    const int wm = (wid >> 2) * 64;
    const int wn = (wid & 3) * 32;
    const int nb = KB1;

    auto issue = [&](int kb) {
        const uint32_t stage = sb + SM_TILES + (kb % NSTAGE) * (2 * PLANE_B);
        const char* asrc = (const char*)a1 + ((size_t)(a1base + (bm >> 7) * KB1 + kb)) * BLKB;
        const char* wsrc = (const char*)w1 + ((size_t)((bn >> 7) * KB1 + kb)) * BLKB;
        #pragma unroll
        for (int j = 0; j < 4; j++) {
            uint32_t off = (uint32_t)(tid * 4 + j) * 16;
            CP_ASYNC16(stage + off, asrc + off);
            CP_ASYNC16(stage + PLANE_B + off, wsrc + off);
        }
        CP_COMMIT();
    };

    float acc[4][4][4];
    ZERO_ACC4(acc);

    issue(0);
    if (nb > 1) issue(1);

    for (int kb = 0; kb < nb; kb++) {
        if (kb + 1 < nb) { CP_WAIT1(); } else { CP_WAIT0(); }
        __syncthreads();
        if (kb + 2 < nb) issue(kb + 2);
        const uint32_t stage = sb + SM_TILES + (kb % NSTAGE) * (2 * PLANE_B);

        #pragma unroll
        for (int ks = 0; ks < 4; ks++) {
            uint32_t ah[4][4], bh[4][2];
            {
                const int arow = wm + (lane & 15);
                const int acol = ks * 32 + ((lane >> 4) << 4);
                #pragma unroll
                for (int mt = 0; mt < 4; mt++) {
                    uint32_t off = SWZ((uint32_t)((arow + mt * 16) * 128 + acol));
                    LDSM4(ah[mt], stage + off);
                }
            }
            {
                const int brow = wn + (lane & 7) + ((lane >> 4) << 3);
                const int bcol = ks * 32 + (((lane >> 3) & 1) << 4);
                #pragma unroll
                for (int p2 = 0; p2 < 2; p2++) {
                    uint32_t off = SWZ((uint32_t)((brow + p2 * 16) * 128 + bcol));
                    uint32_t r[4];
                    LDSM4(r, stage + PLANE_B + off);
                    bh[p2 * 2][0] = r[0]; bh[p2 * 2][1] = r[1];
                    bh[p2 * 2 + 1][0] = r[2]; bh[p2 * 2 + 1][1] = r[3];
                }
            }
            #pragma unroll
            for (int mt = 0; mt < 4; mt++)
                #pragma unroll
                for (int nt = 0; nt < 4; nt++)
                    mma_f16(acc[mt][nt], ah[mt], bh[nt]);
        }
    }

    if (mode == 0) {
        #pragma unroll
        for (int nt = 0; nt < 4; nt++) {
            const int n0 = bn + wn + nt * 8 + 2 * (lane & 3);
            float bias0 = bias ? bias[n0] : 0.f;
            float bias1 = bias ? bias[n0 + 1] : 0.f;
            #pragma unroll
            for (int mt = 0; mt < 4; mt++) {
                const int m0 = bm + wm + mt * 16 + (lane >> 2);
                float2 v0 = make_float2(acc[mt][nt][0] + bias0, acc[mt][nt][1] + bias1);
                float2 v1 = make_float2(acc[mt][nt][2] + bias0, acc[mt][nt][3] + bias1);
                *(float2*)&C[(size_t)m0 * N + n0] = v0;
                *(float2*)&C[(size_t)(m0 + 8) * N + n0] = v1;
            }
        }
        return;
    }

    // 128-row fused LSTM epilogue (set encoder; c_in == 0)
    __syncthreads();
    float* sg = (float*)(smem + SM_TILES);
    #pragma unroll
    for (int nt = 0; nt < 4; nt++) {
        const int ln = wn + nt * 8 + 2 * (lane & 3);
        const float bias0 = bias[bn + ln];
        const float bias1 = bias[bn + ln + 1];
        #pragma unroll
        for (int mt = 0; mt < 4; mt++) {
            const int lm = wm + mt * 16 + (lane >> 2);
            sg[lm * SGPAD + ln]           = acc[mt][nt][0] + bias0;
            sg[lm * SGPAD + ln + 1]       = acc[mt][nt][1] + bias1;
            sg[(lm + 8) * SGPAD + ln]     = acc[mt][nt][2] + bias0;
            sg[(lm + 8) * SGPAD + ln + 1] = acc[mt][nt][3] + bias1;
        }
    }
    __syncthreads();
    const int gu_base = bn >> 2;
    char* ht = (char*)ht_out;
    for (int i = tid; i < 128 * 32; i += 256) {
        const int u = i & 31, mrow = i >> 5;
        const float* row = sg + mrow * SGPAD + u * 4;
        float gi_ = row[0], gg_ = row[2], go_ = row[3];
        const int gm = bm + mrow;
        const int ug = gu_base + u;
        const size_t ci = (size_t)gm * Hd + ug;
        float si = 1.f / (1.f + expf(-gi_));
        float so = 1.f / (1.f + expf(-go_));
        float cn = si * tanhf(gg_);
        float hn = so * tanhf(cn);
        c_out[ci] = cn;
        if (h_f32) h_f32[ci] = hn;
        *(__half*)(ht + tlo(gm, ug, 16)) = __float2half_rn(hn);
    }
}

// ---------------- conversion / pre-tiling kernels (hi plane only) -----------
__device__ __forceinline__ void conv_perm_one(const float* s, __half* dst, int K, int i)
{
    int np = i / K, k = i - np * K;
    int u = np >> 2, g = np & 3;
    float x = s[(size_t)(g * Hd + u) * K + k];
    *(__half*)((char*)dst + tlo(np, k, K >> 6)) = __float2half_rn(x);
}

__global__ void conv_perm_tl(const float* __restrict__ s, __half* __restrict__ dst, int K)
{
    int i = blockIdx.x * blockDim.x + threadIdx.x;
    if (i >= G4H * K) return;
    conv_perm_one(s, dst, K, i);
}

__global__ void conv_pair_perm(const float* __restrict__ s0, __half* __restrict__ d0,
                               const float* __restrict__ s1, __half* __restrict__ d1)
{
    int i = blockIdx.x * blockDim.x + threadIdx.x;
    if (i < G4H * Hd) conv_perm_one(s0, d0, Hd, i);
    else if (i < 2 * G4H * Hd) conv_perm_one(s1, d1, Hd, i - G4H * Hd);
}

__global__ void conv_tl(const float* __restrict__ s, __half* __restrict__ dst,
                        int rows, int K)
{
    int i = blockIdx.x * blockDim.x + threadIdx.x;
    if (i >= rows * K) return;
    int np = i / K, k = i - np * K;
    *(__half*)((char*)dst + tlo(np, k, K >> 6)) = __float2half_rn(s[(size_t)np * K + k]);
}

// fused: attention (blocks 0..511) + bias prep / m fill (blocks 512+)
__global__ void prep_attn(const int* __restrict__ inp, const float* __restrict__ mask,
                          const float* __restrict__ emb, const float* __restrict__ attn_w,
                          const float* __restrict__ attn_b, __half* __restrict__ rtl,
                          const float* sb1, const float* sb2, float* so,
                          const float* gb1, const float* gb2, float* go,
                          const float* mb1, const float* mb2, float* mo,
                          const float* db1, const float* db2, float* dopt,
                          float* m)
{
    __shared__ float aw[Wln];
    __shared__ int   idxs[Wln];
    const int tid = threadIdx.x;

    if (blockIdx.x >= Bsz) {
        int i = (blockIdx.x - Bsz) * 256 + tid;
        if (i < 4 * G4H) {
            int set = i >> 12, np = i & (G4H - 1);
            int u = np >> 2, g = np & 3;
            int src = g * Hd + u;
            float v; float* o;
            if (set == 0)      { v = sb1[src] + sb2[src]; o = so; }
            else if (set == 1) { v = gb1[src] + gb2[src]; o = go; }
            else if (set == 2) { v = mb1[src] + mb2[src]; o = mo; }
            else               { v = db1[src] + db2[src]; o = dopt; }
            o[np] = v;
        } else if (i < 4 * G4H + Bsz) {
            m[i - 4 * G4H] = 1.f;
        }
        return;
    }

    const int b = blockIdx.x;
    const int lane = tid & 31, wrp = tid >> 5;
    if (tid < Wln) idxs[tid] = inp[b * Wln + tid];
    __syncthreads();
    const float* w2 = attn_w + Hd;
    for (int wi = wrp; wi < Wln; wi += 8) {
        const float* e = emb + (size_t)idxs[wi] * Hd;
        float acc = 0.f;
        for (int k = lane; k < Hd; k += 32) acc += e[k] * w2[k];
        #pragma unroll
        for (int o = 16; o; o >>= 1) acc += __shfl_xor_sync(0xffffffffu, acc, o);
        if (lane == 0) {
            float a = 1.f / (1.f + expf(-(acc + attn_b[0])));
            aw[wi] = a * mask[wi * Bsz + b];
        }
    }
    __syncthreads();
    char* d = (char*)rtl;
    for (int hh = tid; hh < Hd; hh += 256) {
        float acc = 0.f;
        #pragma unroll 5
        for (int wi = 0; wi < Wln; wi++)
            acc += aw[wi] * emb[(size_t)idxs[wi] * Hd + hh];
        *(__half*)(d + tlo(b, hh, 16)) = __float2half_rn(acc);
    }
}

// zero the FULL tiled h buffer
__global__ void zero_htl(__half* htl, int n2)
{
    int i = blockIdx.x * blockDim.x + threadIdx.x;
    if (i < n2) htl[i] = __float2half_rn(0.f);
}

// ---------------- host orchestration ----------------
extern "C" void kernel_launch(void* const* d_in, const int* in_sizes, int n_in,
                              void* d_out, int out_size)
{
    const int s = (in_sizes[3] == 1) ? 1 : 0;

    const int*   input_var  = (const int*)  d_in[0];
    const float* input_mask = (const float*)d_in[1];
    const int*   target_var = (const int*)  d_in[2];
    const float* embedding  = (const float*)d_in[3 + s];
    const float* attn_w     = (const float*)d_in[4 + s];
    const float* attn_b     = (const float*)d_in[5 + s];
    const float* set_Wih    = (const float*)d_in[6 + s];
    const float* set_bih    = (const float*)d_in[8 + s];
    const float* set_bhh    = (const float*)d_in[9 + s];
    const float* gen_Whh    = (const float*)d_in[14 + s];
    const float* gen_bih    = (const float*)d_in[15 + s];
    const float* gen_bhh    = (const float*)d_in[16 + s];
    const float* gen_outW   = (const float*)d_in[17 + s];
    const float* gen_outb   = (const float*)d_in[18 + s];
    const float* menc_Wih   = (const float*)d_in[19 + s];
    const float* menc_Whh   = (const float*)d_in[20 + s];
    const float* menc_bih   = (const float*)d_in[21 + s];
    const float* menc_bhh   = (const float*)d_in[22 + s];
    const float* dec_Wih    = (const float*)d_in[25 + s];
    const float* dec_Whh    = (const float*)d_in[26 + s];
    const float* dec_bih    = (const float*)d_in[27 + s];
    const float* dec_bhh    = (const float*)d_in[28 + s];
    const float* dec_outW   = (const float*)d_in[29 + s];
    const float* dec_outb   = (const float*)d_in[30 + s];
    float* out = (float*)d_out;

    float *c, *mm, *m, *hA32, *hB32, *pbs, *pbg, *pbm, *pbd, *pgm, *ptab;
    cudaGetSymbolAddress((void**)&c,    d_c);
    cudaGetSymbolAddress((void**)&mm,   d_mm);
    cudaGetSymbolAddress((void**)&m,    d_m);
    cudaGetSymbolAddress((void**)&hA32, d_hA32);
    cudaGetSymbolAddress((void**)&hB32, d_hB32);
    cudaGetSymbolAddress((void**)&pbs, pb_set);  cudaGetSymbolAddress((void**)&pbg, pb_gen);
    cudaGetSymbolAddress((void**)&pbm, pb_menc); cudaGetSymbolAddress((void**)&pbd, pb_dec);
    cudaGetSymbolAddress((void**)&pgm, pg_menc); cudaGetSymbolAddress((void**)&ptab, d_ptab);
    __half *etl, *wstl, *wgtl, *wmitl, *wmhtl, *wditl, *wdhtl, *wotl;
    __half *hAt, *hBt, *rt, *mstl, *hallt;
    cudaGetSymbolAddress((void**)&etl,   e_tl);
    cudaGetSymbolAddress((void**)&wstl,  wset_tl);
    cudaGetSymbolAddress((void**)&wgtl,  wgen_tl);
    cudaGetSymbolAddress((void**)&wmitl, wmi_tl);
    cudaGetSymbolAddress((void**)&wmhtl, wmh_tl);
    cudaGetSymbolAddress((void**)&wditl, wdi_tl);
    cudaGetSymbolAddress((void**)&wdhtl, wdh_tl);
    cudaGetSymbolAddress((void**)&wotl,  wo_tl);
    cudaGetSymbolAddress((void**)&hAt,   hA_tl);
    cudaGetSymbolAddress((void**)&hBt,   hB_tl);
    cudaGetSymbolAddress((void**)&rt,    r_tl);
    cudaGetSymbolAddress((void**)&mstl,  msg_tl);
    cudaGetSymbolAddress((void**)&hallt, hall_tl);

    cudaFuncSetAttribute(gemm_tc1,  cudaFuncAttributeMaxDynamicSharedMemorySize, SMEM_N1);
    cudaFuncSetAttribute(gen_loop,  cudaFuncAttributeMaxDynamicSharedMemorySize, SMEM_P);
    cudaFuncSetAttribute(menc_loop, cudaFuncAttributeMaxDynamicSharedMemorySize, SMEM_P);
    cudaFuncSetAttribute(dec_loop,  cudaFuncAttributeMaxDynamicSharedMemorySize, SMEM_P);

    const dim3 pg(32, 8);                        // persistent grid: 256 CTAs

    // L0: both gen-phase weight conversions fused
    conv_pair_perm<<<(2 * G4H * Hd + 255) / 256, 256>>>(set_Wih, wstl, gen_Whh, wgtl);
    // L1: attention + all bias preps + m fill fused
    prep_attn<<<Bsz + (4 * G4H + Bsz + 255) / 256, 256>>>(
        input_var, input_mask, embedding, attn_w, attn_b, rt,
        set_bih, set_bhh, pbs, gen_bih, gen_bhh, pbg,
        menc_bih, menc_bhh, pbm, dec_bih, dec_bhh, pbd, m);
    // L2: set encoder cell -> c (gmem) + hAt tiled
    gemm_tc1<<<dim3(32, 4), 256, SMEM_N1>>>(nullptr, G4H, rt, 0, wstl, 16, pbs,
                                            1, c, nullptr, hAt);
    // L3: gen persistent loop (group barriers)
    gen_loop<<<pg, 256, SMEM_P>>>(wgtl, pbg, gen_outW, gen_outb, c, mm, m,
                                  hAt, hBt, hA32, hB32, mstl);

    // ---- menc phase ----
    conv_perm_tl<<<(G4H * MVd + 255) / 256, 256>>>(menc_Wih, wmitl, MVd);
    conv_perm_tl<<<(G4H * Hd + 255) / 256, 256>>>(menc_Whh, wmhtl, Hd);
    gemm_tc1<<<dim3(32, (Ld * Bsz) / 128), 256, SMEM_N1>>>(pgm, G4H, mstl, 0,
                                                           wmitl, 1, pbm, 0,
                                                           nullptr, nullptr, nullptr);
    zero_htl<<<(2 * Bsz * Hd + 255) / 256, 256>>>(hAt, 2 * Bsz * Hd);
    menc_loop<<<pg, 256, SMEM_P>>>(wmhtl, pgm, c, mm, hAt, hBt);
    // Ld = 30 even -> final menc h tiled in hAt; c written back to gmem

    // ---- dec phase: vocab-factorized input gates ----
    conv_pair_perm<<<(2 * G4H * Hd + 255) / 256, 256>>>(dec_Wih, wditl, dec_Whh, wdhtl);
    conv_tl<<<(Vb * Hd + 255) / 256, 256>>>(embedding, etl, Vb, Hd);
    gemm_tc1<<<dim3(32, Vb / 128), 256, SMEM_N1>>>(ptab, G4H, etl, 0,
                                                   wditl, 16, pbd, 0,
                                                   nullptr, nullptr, nullptr);
    dec_loop<<<pg, 256, SMEM_P>>>(wdhtl, ptab, target_var, c, hAt, hallt);

    // ---- logits (1-product fp16) ----
    conv_tl<<<(Vb * Hd + 255) / 256, 256>>>(dec_outW, wotl, Vb, Hd);
    gemm_tc1<<<dim3(Vb / 128, (Tln * Bsz) / 128), 256, SMEM_N1>>>(
        out, Vb, hallt, 0, wotl, 16, dec_outb, 0, nullptr, nullptr, nullptr);
}